// round 11
// baseline (speedup 1.0000x reference)
#include <cuda_runtime.h>
#include <cuda_fp16.h>
#include <cstdint>

#define N_NODES 100000
#define N_EDGES 640000
#define HDIM 128
#define H2DIM 256
#define EDIM 16

// ---------------- scratch (device globals) ------------------------------------
__device__ __half g_PQh [(size_t)N_NODES * 256];   // fp16: [0:128]=node@W1, [128:256]=node@W2
__device__ __half g_MSGh[(size_t)N_EDGES * HDIM];  // fp16 pre-BN messages
__device__ float  g_Y   [(size_t)N_NODES * HDIM];  // scatter target (fp32 accum)
__device__ float  g_H1  [(size_t)N_NODES * H2DIM]; // fp32 MLP intermediates (error budget)
__device__ float  g_H2  [(size_t)N_NODES * H2DIM];
// BN stat slots: [0,128)=msg, [128,384)=bn1, [384,640)=bn2
__device__ float g_sum[640];
__device__ float g_sq [640];
__device__ float g_scaleArr[640];
__device__ float g_shiftArr[640];

// packed tf32 weights (node + MLP)
#define OFF_NODE 0        // [128][256]  W1 | W2
#define OFF_M1   32768    // [128][256]
#define OFF_M2   65536    // [256][256]
#define OFF_M3   131072   // [256][128]
#define W_TOTAL  163840
__device__ unsigned g_Wbuf[W_TOTAL];
// edge weights fp16, [n][k] layout: n=0..127 rows, k 0..127 = W3, 128..143 = We, stride 160
#define WEH_STRIDE 160
__device__ __half g_WedgeH[128 * WEH_STRIDE];

// ---------------- helpers ------------------------------------------------------
__device__ __forceinline__ unsigned f2tf32(float x) {
    unsigned r;
    asm("cvt.rna.tf32.f32 %0, %1;" : "=r"(r) : "f"(x));
    return r;
}

__device__ __forceinline__ void mma_tf32(float* c, const unsigned* a, const unsigned* b) {
    asm volatile(
        "mma.sync.aligned.m16n8k8.row.col.f32.tf32.tf32.f32 "
        "{%0,%1,%2,%3}, {%4,%5,%6,%7}, {%8,%9}, {%0,%1,%2,%3};"
        : "+f"(c[0]), "+f"(c[1]), "+f"(c[2]), "+f"(c[3])
        : "r"(a[0]), "r"(a[1]), "r"(a[2]), "r"(a[3]), "r"(b[0]), "r"(b[1]));
}

__device__ __forceinline__ void mma_f16(float* c, const unsigned* a, const unsigned* b) {
    asm volatile(
        "mma.sync.aligned.m16n8k16.row.col.f32.f16.f16.f32 "
        "{%0,%1,%2,%3}, {%4,%5,%6,%7}, {%8,%9}, {%0,%1,%2,%3};"
        : "+f"(c[0]), "+f"(c[1]), "+f"(c[2]), "+f"(c[3])
        : "r"(a[0]), "r"(a[1]), "r"(a[2]), "r"(a[3]), "r"(b[0]), "r"(b[1]));
}

__device__ __forceinline__ void cp16(uint32_t dst, const void* src, bool pred) {
    int sz = pred ? 16 : 0;
    asm volatile("cp.async.cg.shared.global [%0], [%1], 16, %2;"
                 :: "r"(dst), "l"(src), "r"(sz));
}
__device__ __forceinline__ void cp_commit() { asm volatile("cp.async.commit_group;"); }
template <int N> __device__ __forceinline__ void cp_wait() {
    asm volatile("cp.async.wait_group %0;" :: "n"(N));
}
__device__ __forceinline__ uint32_t s2u(const void* p) {
    uint32_t a;
    asm("{ .reg .u64 t; cvta.to.shared.u64 t, %1; cvt.u32.u64 %0, t; }" : "=r"(a) : "l"(p));
    return a;
}
__device__ __forceinline__ uint2 pack_half4(float4 v) {
    __half2 h0 = __floats2half2_rn(v.x, v.y);
    __half2 h1 = __floats2half2_rn(v.z, v.w);
    uint2 u;
    u.x = *(unsigned*)&h0;
    u.y = *(unsigned*)&h1;
    return u;
}
__device__ __forceinline__ float4 unpack_half4(uint2 u) {
    __half2 h0 = *(__half2*)&u.x;
    __half2 h1 = *(__half2*)&u.y;
    float2 f0 = __half22float2(h0);
    float2 f1 = __half22float2(h1);
    return make_float4(f0.x, f0.y, f1.x, f1.y);
}
__device__ __forceinline__ unsigned h2_from_f2(float2 f) {
    __half2 h = __float22half2_rn(f);
    return *(unsigned*)&h;
}

// GEMM smem geometry (128-row A tile, 3 stages, fp32 A)
#define G_AS_STAGE 18432             // 128*36*4
#define G_BS_STAGE 17408             // 32*136*4
#define G_AS_BYTES (3 * G_AS_STAGE)  // 55296
#define G_BS_BYTES (3 * G_BS_STAGE)  // 52224
#define G_PIPE (G_AS_BYTES + G_BS_BYTES)  // 107520
// edge smem geometry: A 64x36 fp32, B 128x40 fp16, 2 stages
#define E_AS_STAGE 9216              // 64*36*4
#define E_BSH_STAGE 10240            // 128*40*2
#define E_AS_BYTES (2 * E_AS_STAGE)  // 18432
#define E_PIPE (E_AS_BYTES + 2 * E_BSH_STAGE)  // 38912

// ---------------- utility kernels ----------------------------------------------
#define PREP_TOTAL (W_TOTAL + 128 * WEH_STRIDE)   // 163840 + 20480 = 184320
__global__ void prep_kernel(const float* __restrict__ W1, const float* __restrict__ W2,
                            const float* __restrict__ W3, const float* __restrict__ We,
                            const float* __restrict__ Wm1, const float* __restrict__ Wm2,
                            const float* __restrict__ Wm3) {
    int i = blockIdx.x * blockDim.x + threadIdx.x;
    if (i < 32768) {
        int k = i >> 8, n = i & 255;
        float v = (n < 128) ? W1[k * 128 + n] : W2[k * 128 + (n - 128)];
        g_Wbuf[OFF_NODE + i] = f2tf32(v);
    } else if (i < 65536) {
        g_Wbuf[OFF_M1 + (i - 32768)] = f2tf32(Wm1[i - 32768]);
    } else if (i < 131072) {
        g_Wbuf[OFF_M2 + (i - 65536)] = f2tf32(Wm2[i - 65536]);
    } else if (i < W_TOTAL) {
        g_Wbuf[OFF_M3 + (i - 131072)] = f2tf32(Wm3[i - 131072]);
    } else if (i < PREP_TOTAL) {
        int j = i - W_TOTAL;
        int n = j / WEH_STRIDE, k = j % WEH_STRIDE;
        float v = 0.f;
        if (k < 128)      v = W3[k * 128 + n];
        else if (k < 144) v = We[(k - 128) * 128 + n];
        g_WedgeH[j] = __float2half_rn(v);
    }
}

__global__ void zero_y_stats_kernel() {
    size_t i = (size_t)blockIdx.x * blockDim.x + threadIdx.x;
    const size_t tot = (size_t)N_NODES * HDIM;
    const size_t stride = (size_t)gridDim.x * blockDim.x;
    for (size_t p = i; p < tot; p += stride) g_Y[p] = 0.f;
    if (i < 640) { g_sum[i] = 0.f; g_sq[i] = 0.f; }
}

__global__ void bn_finalize_kernel(const float* __restrict__ g,
                                   const float* __restrict__ b,
                                   int off, int cols, float invCnt) {
    int c = blockIdx.x * blockDim.x + threadIdx.x;
    if (c < cols) {
        float mean = g_sum[off + c] * invCnt;
        float var  = fmaxf(g_sq[off + c] * invCnt - mean * mean, 0.f);
        float a = g[c] * rsqrtf(var + 1e-5f);
        g_scaleArr[off + c] = a;
        g_shiftArr[off + c] = fmaf(-mean, a, b[c]);
    }
}

extern __shared__ char smem_raw[];

// ---------------- 3-stage pipelined tf32 GEMM with fused BN ---------------------
// C[M,NC] = act(A) @ Wu (+cBias); act = relu(aScale[k]*x+aShift[k]) if aScale.
// outHalf: store C as fp16 (PQ output).
__global__ void __launch_bounds__(256, 2) gemm_mma_kernel(
    const float* __restrict__ A, const unsigned* __restrict__ Wu,
    void* __restrict__ Cout, int M, int K, int NC, int outHalf,
    const float* __restrict__ aScale, const float* __restrict__ aShift,
    const float* __restrict__ cBias,
    float* __restrict__ sSum, float* __restrict__ sSq)
{
    float    (*As)[128][36]  = reinterpret_cast<float(*)[128][36]>(smem_raw);
    unsigned (*Bs)[32][136]  = reinterpret_cast<unsigned(*)[32][136]>(smem_raw + G_AS_BYTES);
    float    (*Cs)[132]      = reinterpret_cast<float(*)[132]>(smem_raw);   // overlay
    float* scs  = (float*)(smem_raw + G_PIPE);          // 256
    float* shs  = scs + 256;                            // 256
    float* red0 = shs + 256;                            // 128
    float* red1 = red0 + 128;                           // 128

    const int tid = threadIdx.x, lane = tid & 31, warp = tid >> 5;
    const int wm = (warp & 3) * 32, wn = (warp >> 2) * 64;
    const int bm = blockIdx.y * 128, bn = blockIdx.x * 128;
    const bool useBN = (aScale != nullptr);

    const uint32_t AsAddr = s2u(smem_raw);
    const uint32_t BsAddr = AsAddr + G_AS_BYTES;

    if (useBN && tid < K) { scs[tid] = aScale[tid]; shs[tid] = aShift[tid]; }

    auto issue_copy = [&](int t) {
        const int s = t % 3;
        const int k0 = t * 32;
#pragma unroll
        for (int l = 0; l < 4; l++) {
            int c = tid + l * 256;
            int row = c >> 3, cc = c & 7;
            int grow = bm + row;
            const float* src = A + (size_t)grow * K + k0 + cc * 4;
            uint32_t dst = AsAddr + (uint32_t)(s * G_AS_STAGE + (row * 36 + cc * 4) * 4);
            cp16(dst, src, grow < M);
        }
#pragma unroll
        for (int l = 0; l < 4; l++) {
            int c = tid + l * 256;
            int row = c >> 5, cc = c & 31;
            const unsigned* src = Wu + (size_t)(k0 + row) * NC + bn + cc * 4;
            uint32_t dst = BsAddr + (uint32_t)(s * G_BS_STAGE + (row * 136 + cc * 4) * 4);
            cp16(dst, src, true);
        }
        cp_commit();
    };

    float acc[2][8][4];
#pragma unroll
    for (int mt = 0; mt < 2; mt++)
#pragma unroll
        for (int nt = 0; nt < 8; nt++)
#pragma unroll
            for (int i = 0; i < 4; i++) acc[mt][nt][i] = 0.f;

    const int T = K >> 5;
    issue_copy(0);
    if (T > 1) issue_copy(1);

    for (int t = 0; t < T; t++) {
        if (t + 2 < T)      { issue_copy(t + 2); cp_wait<2>(); }
        else if (t + 1 < T) { cp_wait<1>(); }
        else                { cp_wait<0>(); }
        __syncthreads();
        const int s = t % 3;
        const int k0 = t * 32;
#pragma unroll
        for (int q = 0; q < 4; q++) {
            const int kr = q * 8 + (lane & 3);
            float s0 = 1.f, h0 = 0.f, s4 = 1.f, h4 = 0.f;
            if (useBN) {
                s0 = scs[k0 + kr];     h0 = shs[k0 + kr];
                s4 = scs[k0 + kr + 4]; h4 = shs[k0 + kr + 4];
            }
            unsigned af[2][4], bf[8][2];
#pragma unroll
            for (int mt = 0; mt < 2; mt++) {
                int m = wm + mt * 16 + (lane >> 2);
                float a0 = As[s][m][kr],     a1 = As[s][m + 8][kr];
                float a2 = As[s][m][kr + 4], a3 = As[s][m + 8][kr + 4];
                if (useBN) {
                    a0 = fmaxf(fmaf(a0, s0, h0), 0.f);
                    a1 = fmaxf(fmaf(a1, s0, h0), 0.f);
                    a2 = fmaxf(fmaf(a2, s4, h4), 0.f);
                    a3 = fmaxf(fmaf(a3, s4, h4), 0.f);
                }
                af[mt][0] = f2tf32(a0); af[mt][1] = f2tf32(a1);
                af[mt][2] = f2tf32(a2); af[mt][3] = f2tf32(a3);
            }
#pragma unroll
            for (int nt = 0; nt < 8; nt++) {
                int n = wn + nt * 8 + (lane >> 2);
                bf[nt][0] = Bs[s][kr][n];
                bf[nt][1] = Bs[s][kr + 4][n];
            }
#pragma unroll
            for (int mt = 0; mt < 2; mt++)
#pragma unroll
                for (int nt = 0; nt < 8; nt++)
                    mma_tf32(acc[mt][nt], af[mt], bf[nt]);
        }
        __syncthreads();
    }

    // ---------------- epilogue: stage -> smem, warp-per-row coalesced ----------
#pragma unroll
    for (int mt = 0; mt < 2; mt++)
#pragma unroll
        for (int half = 0; half < 2; half++) {
            int r = wm + mt * 16 + (lane >> 2) + half * 8;
#pragma unroll
            for (int nt = 0; nt < 8; nt++) {
                int cl = wn + nt * 8 + 2 * (lane & 3);
                float2 v; v.x = acc[mt][nt][half * 2 + 0]; v.y = acc[mt][nt][half * 2 + 1];
                *(float2*)&Cs[r][cl] = v;
            }
        }
    if (sSum && tid < 128) { red0[tid] = 0.f; red1[tid] = 0.f; }
    __syncthreads();

    float4 bias = make_float4(0.f, 0.f, 0.f, 0.f);
    if (cBias) bias = *(const float4*)(cBias + bn + lane * 4);
    float psum[4] = {0.f, 0.f, 0.f, 0.f}, psq[4] = {0.f, 0.f, 0.f, 0.f};

#pragma unroll
    for (int i = 0; i < 16; i++) {
        int r = warp * 16 + i;
        int R = bm + r;
        if (R < M) {
            float4 v = *(const float4*)&Cs[r][lane * 4];
            v.x += bias.x; v.y += bias.y; v.z += bias.z; v.w += bias.w;
            if (outHalf) {
                __half* Ch = (__half*)Cout;
                *(uint2*)(Ch + (size_t)R * NC + bn + lane * 4) = pack_half4(v);
            } else {
                float* Cf = (float*)Cout;
                *(float4*)(Cf + (size_t)R * NC + bn + lane * 4) = v;
            }
            psum[0] += v.x; psum[1] += v.y; psum[2] += v.z; psum[3] += v.w;
            psq[0] += v.x * v.x; psq[1] += v.y * v.y;
            psq[2] += v.z * v.z; psq[3] += v.w * v.w;
        }
    }

    if (sSum) {
        __syncthreads();
#pragma unroll
        for (int j = 0; j < 4; j++) {
            atomicAdd(&red0[lane * 4 + j], psum[j]);
            atomicAdd(&red1[lane * 4 + j], psq[j]);
        }
        __syncthreads();
        if (tid < 128) {
            atomicAdd(&sSum[bn + tid], red0[tid]);
            atomicAdd(&sSq [bn + tid], red1[tid]);
        }
    }
}

// ---------------- edge message kernel: fp16 HMMA m16n8k16 ----------------------
// MSG[e] = edge_rep[e]@W3 + edge_attr[e]@We + be + P[src[e]] + Q[dst[e]], + stats
// A: fp32 in smem (64x36), converted to half2 at fragment load.
// B: fp16 [n][k] in smem (128x40, conflict-free), from g_WedgeH.
__global__ void __launch_bounds__(256, 3) edge_msg_kernel(
    const float* __restrict__ edge_rep, const float* __restrict__ edge_attr,
    const int* __restrict__ src, const int* __restrict__ dst,
    const float* __restrict__ be)
{
    float  (*As)[64][36]  = reinterpret_cast<float(*)[64][36]>(smem_raw);
    __half (*Bs)[128][40] = reinterpret_cast<__half(*)[128][40]>(smem_raw + E_AS_BYTES);
    float  (*Cs)[132]     = reinterpret_cast<float(*)[132]>(smem_raw);   // overlay
    float* red0 = (float*)(smem_raw + E_PIPE);
    float* red1 = red0 + 128;

    const int tid = threadIdx.x, lane = tid & 31, warp = tid >> 5;
    const int wm = (warp & 1) * 32, wn = (warp >> 1) * 32;
    const int g  = lane >> 2;
    const int c2 = (lane & 3) * 2;
    const size_t bm = (size_t)blockIdx.x * 64;

    const uint32_t AsAddr = s2u(smem_raw);
    const uint32_t BsAddr = AsAddr + E_AS_BYTES;

    // L2 prefetch of the P/Q gather rows (hidden behind mainloop)
    if (tid < 128) {
        int e0 = (int)bm + (tid >> 1);
        const __half* row = (tid & 1) ? (g_PQh + (size_t)dst[e0] * 256 + 128)
                                      : (g_PQh + (size_t)src[e0] * 256);
        asm volatile("prefetch.global.L2 [%0];" :: "l"(row));
        asm volatile("prefetch.global.L2 [%0];" :: "l"(row + 64));
    }

    auto issue_copy = [&](int t) {
        const int s = t & 1;
        if (t < 4) {
            const int k0 = t * 32;
            // A: 64 rows x 32 floats = 512 chunks / 256 thr = 2
#pragma unroll
            for (int l = 0; l < 2; l++) {
                int c = tid + l * 256;
                int row = c >> 3, cc = c & 7;
                const float* sp = edge_rep + (bm + row) * HDIM + k0 + cc * 4;
                uint32_t dp = AsAddr + (uint32_t)(s * E_AS_STAGE + (row * 36 + cc * 4) * 4);
                cp16(dp, sp, true);
            }
            // B: 128 rows x 32 halfs = 512 chunks(16B=8h) / 256 thr = 2
#pragma unroll
            for (int l = 0; l < 2; l++) {
                int c = tid + l * 256;
                int row = c >> 2, cc = c & 3;
                const __half* sp = g_WedgeH + (size_t)row * WEH_STRIDE + k0 + cc * 8;
                uint32_t dp = BsAddr + (uint32_t)(s * E_BSH_STAGE + (row * 40 + cc * 8) * 2);
                cp16(dp, sp, true);
            }
        } else {
            // tail K=16: A = edge_attr (64 rows x 16 floats = 256 chunks)
            {
                int row = tid >> 2, cc = tid & 3;
                const float* sp = edge_attr + (bm + row) * EDIM + cc * 4;
                uint32_t dp = AsAddr + (uint32_t)(s * E_AS_STAGE + (row * 36 + cc * 4) * 4);
                cp16(dp, sp, true);
            }
            // B tail: 128 rows x 16 halfs = 256 chunks
            {
                int row = tid >> 1, cc = tid & 1;
                const __half* sp = g_WedgeH + (size_t)row * WEH_STRIDE + 128 + cc * 8;
                uint32_t dp = BsAddr + (uint32_t)(s * E_BSH_STAGE + (row * 40 + cc * 8) * 2);
                cp16(dp, sp, true);
            }
        }
        cp_commit();
    };

    float acc[2][4][4];
#pragma unroll
    for (int mt = 0; mt < 2; mt++)
#pragma unroll
        for (int nt = 0; nt < 4; nt++)
#pragma unroll
            for (int i = 0; i < 4; i++) acc[mt][nt][i] = 0.f;

    issue_copy(0);

#pragma unroll
    for (int t = 0; t < 5; t++) {
        cp_wait<0>();
        __syncthreads();
        if (t + 1 < 5) issue_copy(t + 1);
        const int s = t & 1;
        const int ksteps = (t < 4) ? 2 : 1;
#pragma unroll
        for (int ks = 0; ks < 2; ks++) {
            if (ks >= ksteps) break;
            const int kk = ks * 16;
            unsigned af[2][4], bf[4][2];
#pragma unroll
            for (int mt = 0; mt < 2; mt++) {
                int m = wm + mt * 16 + g;
                af[mt][0] = h2_from_f2(*(const float2*)&As[s][m    ][kk + c2]);
                af[mt][1] = h2_from_f2(*(const float2*)&As[s][m + 8][kk + c2]);
                af[mt][2] = h2_from_f2(*(const float2*)&As[s][m    ][kk + c2 + 8]);
                af[mt][3] = h2_from_f2(*(const float2*)&As[s][m + 8][kk + c2 + 8]);
            }
#pragma unroll
            for (int nt = 0; nt < 4; nt++) {
                int n = wn + nt * 8 + g;
                bf[nt][0] = *(const unsigned*)&Bs[s][n][kk + c2];
                bf[nt][1] = *(const unsigned*)&Bs[s][n][kk + c2 + 8];
            }
#pragma unroll
            for (int mt = 0; mt < 2; mt++)
#pragma unroll
                for (int nt = 0; nt < 4; nt++)
                    mma_f16(acc[mt][nt], af[mt], bf[nt]);
        }
        __syncthreads();
    }

    // ---------------- epilogue: stage -> smem, warp-per-edge coalesced ---------
#pragma unroll
    for (int mt = 0; mt < 2; mt++)
#pragma unroll
        for (int half = 0; half < 2; half++) {
            int r = wm + mt * 16 + g + half * 8;
#pragma unroll
            for (int nt = 0; nt < 4; nt++) {
                int cl = wn + nt * 8 + c2;
                float2 v; v.x = acc[mt][nt][half * 2 + 0]; v.y = acc[mt][nt][half * 2 + 1];
                *(float2*)&Cs[r][cl] = v;
            }
        }
    if (tid < 128) { red0[tid] = 0.f; red1[tid] = 0.f; }
    __syncthreads();

    float4 bev = *(const float4*)(be + lane * 4);
    float psum[4] = {0.f, 0.f, 0.f, 0.f}, psq[4] = {0.f, 0.f, 0.f, 0.f};

#pragma unroll
    for (int i = 0; i < 8; i++) {
        int r = warp * 8 + i;
        size_t e = bm + r;
        int s = src[e], d = dst[e];
        float4 pv = unpack_half4(*(const uint2*)(g_PQh + (size_t)s * 256 + lane * 4));
        float4 qv = unpack_half4(*(const uint2*)(g_PQh + (size_t)d * 256 + 128 + lane * 4));
        float4 v = *(const float4*)&Cs[r][lane * 4];
        v.x += pv.x + qv.x + bev.x;
        v.y += pv.y + qv.y + bev.y;
        v.z += pv.z + qv.z + bev.z;
        v.w += pv.w + qv.w + bev.w;
        *(uint2*)(g_MSGh + e * HDIM + lane * 4) = pack_half4(v);
        psum[0] += v.x; psum[1] += v.y; psum[2] += v.z; psum[3] += v.w;
        psq[0] += v.x * v.x; psq[1] += v.y * v.y;
        psq[2] += v.z * v.z; psq[3] += v.w * v.w;
    }

    __syncthreads();
#pragma unroll
    for (int j = 0; j < 4; j++) {
        atomicAdd(&red0[lane * 4 + j], psum[j]);
        atomicAdd(&red1[lane * 4 + j], psq[j]);
    }
    __syncthreads();
    if (tid < 128) {
        atomicAdd(&g_sum[tid], red0[tid]);
        atomicAdd(&g_sq [tid], red1[tid]);
    }
}

// ---------------- BN+ReLU+scatter with vector red ------------------------------
__global__ void scatter_kernel(const int* __restrict__ dst) {
    unsigned t = blockIdx.x * blockDim.x + threadIdx.x;
    size_t e = (size_t)(t >> 5);
    int c4 = (t & 31) * 4;
    if (e < (size_t)N_EDGES) {
        int d = dst[e];
        float4 m = unpack_half4(*(const uint2*)(g_MSGh + e * HDIM + c4));
        float v0 = fmaxf(fmaf(m.x, g_scaleArr[c4 + 0], g_shiftArr[c4 + 0]), 0.f);
        float v1 = fmaxf(fmaf(m.y, g_scaleArr[c4 + 1], g_shiftArr[c4 + 1]), 0.f);
        float v2 = fmaxf(fmaf(m.z, g_scaleArr[c4 + 2], g_shiftArr[c4 + 2]), 0.f);
        float v3 = fmaxf(fmaf(m.w, g_scaleArr[c4 + 3], g_shiftArr[c4 + 3]), 0.f);
        float* p = g_Y + (size_t)d * HDIM + c4;
        asm volatile("red.global.add.v4.f32 [%0], {%1,%2,%3,%4};"
                     :: "l"(p), "f"(v0), "f"(v1), "f"(v2), "f"(v3) : "memory");
    }
}

// ---------------- launch ------------------------------------------------------
extern "C" void kernel_launch(void* const* d_in, const int* in_sizes, int n_in,
                              void* d_out, int out_size) {
    const float* node_rep  = (const float*)d_in[0];
    const float* edge_rep  = (const float*)d_in[1];
    const float* edge_attr = (const float*)d_in[2];
    const int*   eidx      = (const int*)d_in[3];
    const float* W1  = (const float*)d_in[4];
    const float* W2  = (const float*)d_in[5];
    const float* W3  = (const float*)d_in[6];
    const float* We  = (const float*)d_in[7];
    const float* be  = (const float*)d_in[8];
    const float* bng = (const float*)d_in[9];
    const float* bnb = (const float*)d_in[10];
    const float* Wm1 = (const float*)d_in[11];
    const float* g1  = (const float*)d_in[12];
    const float* b1  = (const float*)d_in[13];
    const float* Wm2 = (const float*)d_in[14];
    const float* g2  = (const float*)d_in[15];
    const float* b2  = (const float*)d_in[16];
    const float* Wm3 = (const float*)d_in[17];
    const float* bm3 = (const float*)d_in[18];
    float* out = (float*)d_out;

    const int* src = eidx;
    const int* dst = eidx + N_EDGES;

    float *Y, *H1, *H2, *SUM, *SQ, *SCALE, *SHIFT;
    __half* PQh;
    unsigned* WB;
    cudaGetSymbolAddress((void**)&PQh, g_PQh);
    cudaGetSymbolAddress((void**)&Y,  g_Y);
    cudaGetSymbolAddress((void**)&H1, g_H1);
    cudaGetSymbolAddress((void**)&H2, g_H2);
    cudaGetSymbolAddress((void**)&SUM,   g_sum);
    cudaGetSymbolAddress((void**)&SQ,    g_sq);
    cudaGetSymbolAddress((void**)&SCALE, g_scaleArr);
    cudaGetSymbolAddress((void**)&SHIFT, g_shiftArr);
    cudaGetSymbolAddress((void**)&WB, g_Wbuf);

    const int GEMM_SMEM = G_PIPE + 2048 + 1024;   // 110592
    const int EDGE_SMEM = E_PIPE + 1024;          // 39936
    cudaFuncSetAttribute(gemm_mma_kernel, cudaFuncAttributeMaxDynamicSharedMemorySize, GEMM_SMEM);
    cudaFuncSetAttribute(edge_msg_kernel, cudaFuncAttributeMaxDynamicSharedMemorySize, EDGE_SMEM);

    const int MBLK = (N_NODES + 127) / 128;  // 782

    prep_kernel<<<(PREP_TOTAL + 255) / 256, 256>>>(W1, W2, W3, We, Wm1, Wm2, Wm3);
    zero_y_stats_kernel<<<4096, 256>>>();

    // fused node linears: PQ = node_rep @ [W1|W2] -> fp16
    gemm_mma_kernel<<<dim3(2, MBLK), 256, GEMM_SMEM>>>(
        node_rep, WB + OFF_NODE, PQh, N_NODES, HDIM, 256, 1,
        nullptr, nullptr, nullptr, nullptr, nullptr);

    // edge GEMM (fp16 HMMA) + encoder + gathers + BN stats
    edge_msg_kernel<<<N_EDGES / 64, 256, EDGE_SMEM>>>(edge_rep, edge_attr, src, dst, be);

    bn_finalize_kernel<<<1, 128>>>(bng, bnb, 0, 128, 1.f / (float)N_EDGES);

    // BN + ReLU + scatter-sum
    scatter_kernel<<<(N_EDGES * 32) / 256, 256>>>(dst);

    // MLP layer 1: H1(fp32) = Y @ Wm1
    gemm_mma_kernel<<<dim3(2, MBLK), 256, GEMM_SMEM>>>(
        Y, WB + OFF_M1, H1, N_NODES, HDIM, H2DIM, 0,
        nullptr, nullptr, nullptr, SUM + 128, SQ + 128);
    bn_finalize_kernel<<<2, 128>>>(g1, b1, 128, 256, 1.f / (float)N_NODES);

    // MLP layer 2: H2(fp32) = relu(bn1(H1)) @ Wm2
    gemm_mma_kernel<<<dim3(2, MBLK), 256, GEMM_SMEM>>>(
        H1, WB + OFF_M2, H2, N_NODES, H2DIM, H2DIM, 0,
        SCALE + 128, SHIFT + 128, nullptr, SUM + 384, SQ + 384);
    bn_finalize_kernel<<<2, 128>>>(g2, b2, 384, 256, 1.f / (float)N_NODES);

    // MLP layer 3: out = relu(bn2(H2)) @ Wm3 + bm3
    gemm_mma_kernel<<<dim3(1, MBLK), 256, GEMM_SMEM>>>(
        H2, WB + OFF_M3, out, N_NODES, H2DIM, HDIM, 0,
        SCALE + 384, SHIFT + 384, bm3, nullptr, nullptr);
}

// round 12
// speedup vs baseline: 1.0300x; 1.0300x over previous
#include <cuda_runtime.h>
#include <cuda_fp16.h>
#include <cstdint>

#define N_NODES 100000
#define N_EDGES 640000
#define HDIM 128
#define H2DIM 256
#define EDIM 16

// ---------------- scratch (device globals) ------------------------------------
__device__ __half g_PQh [(size_t)N_NODES * 256];   // fp16: [0:128]=node@W1, [128:256]=node@W2
__device__ __half g_MSGh[(size_t)N_EDGES * HDIM];  // fp16 pre-BN messages
__device__ float  g_Y   [(size_t)N_NODES * HDIM];  // scatter target (fp32 accum)
__device__ float  g_H1  [(size_t)N_NODES * H2DIM]; // fp32 MLP intermediates (error budget)
__device__ float  g_H2  [(size_t)N_NODES * H2DIM];
// BN stat slots: [0,128)=msg, [128,384)=bn1, [384,640)=bn2
__device__ float g_sum[640];
__device__ float g_sq [640];
__device__ float g_scaleArr[640];
__device__ float g_shiftArr[640];

// packed tf32 weights (node + MLP)
#define OFF_NODE 0        // [128][256]  W1 | W2
#define OFF_M1   32768    // [128][256]
#define OFF_M2   65536    // [256][256]
#define OFF_M3   131072   // [256][128]
#define W_TOTAL  163840
__device__ unsigned g_Wbuf[W_TOTAL];
// edge weights fp16, [n][k] layout: n=0..127 rows, k 0..127 = W3, 128..143 = We, stride 160
#define WEH_STRIDE 160
__device__ __half g_WedgeH[128 * WEH_STRIDE];

// ---------------- helpers ------------------------------------------------------
__device__ __forceinline__ unsigned f2tf32(float x) {
    unsigned r;
    asm("cvt.rna.tf32.f32 %0, %1;" : "=r"(r) : "f"(x));
    return r;
}

__device__ __forceinline__ void mma_tf32(float* c, const unsigned* a, const unsigned* b) {
    asm volatile(
        "mma.sync.aligned.m16n8k8.row.col.f32.tf32.tf32.f32 "
        "{%0,%1,%2,%3}, {%4,%5,%6,%7}, {%8,%9}, {%0,%1,%2,%3};"
        : "+f"(c[0]), "+f"(c[1]), "+f"(c[2]), "+f"(c[3])
        : "r"(a[0]), "r"(a[1]), "r"(a[2]), "r"(a[3]), "r"(b[0]), "r"(b[1]));
}

__device__ __forceinline__ void mma_f16(float* c, const unsigned* a, const unsigned* b) {
    asm volatile(
        "mma.sync.aligned.m16n8k16.row.col.f32.f16.f16.f32 "
        "{%0,%1,%2,%3}, {%4,%5,%6,%7}, {%8,%9}, {%0,%1,%2,%3};"
        : "+f"(c[0]), "+f"(c[1]), "+f"(c[2]), "+f"(c[3])
        : "r"(a[0]), "r"(a[1]), "r"(a[2]), "r"(a[3]), "r"(b[0]), "r"(b[1]));
}

__device__ __forceinline__ void cp16(uint32_t dst, const void* src, bool pred) {
    int sz = pred ? 16 : 0;
    asm volatile("cp.async.cg.shared.global [%0], [%1], 16, %2;"
                 :: "r"(dst), "l"(src), "r"(sz));
}
__device__ __forceinline__ void cp_commit() { asm volatile("cp.async.commit_group;"); }
template <int N> __device__ __forceinline__ void cp_wait() {
    asm volatile("cp.async.wait_group %0;" :: "n"(N));
}
__device__ __forceinline__ uint32_t s2u(const void* p) {
    uint32_t a;
    asm("{ .reg .u64 t; cvta.to.shared.u64 t, %1; cvt.u32.u64 %0, t; }" : "=r"(a) : "l"(p));
    return a;
}
__device__ __forceinline__ uint2 pack_half4(float4 v) {
    __half2 h0 = __floats2half2_rn(v.x, v.y);
    __half2 h1 = __floats2half2_rn(v.z, v.w);
    uint2 u;
    u.x = *(unsigned*)&h0;
    u.y = *(unsigned*)&h1;
    return u;
}
__device__ __forceinline__ float4 unpack_half4(uint2 u) {
    __half2 h0 = *(__half2*)&u.x;
    __half2 h1 = *(__half2*)&u.y;
    float2 f0 = __half22float2(h0);
    float2 f1 = __half22float2(h1);
    return make_float4(f0.x, f0.y, f1.x, f1.y);
}
__device__ __forceinline__ unsigned h2_from_f2(float2 f) {
    __half2 h = __float22half2_rn(f);
    return *(unsigned*)&h;
}

// GEMM smem geometry (128-row A tile, 3 stages, fp32 A)
#define G_AS_STAGE 18432             // 128*36*4
#define G_BS_STAGE 17408             // 32*136*4
#define G_AS_BYTES (3 * G_AS_STAGE)  // 55296
#define G_BS_BYTES (3 * G_BS_STAGE)  // 52224
#define G_PIPE (G_AS_BYTES + G_BS_BYTES)  // 107520
// edge smem geometry: A 64x40 fp32 (conflict-free), B 128x40 fp16, 2 stages
#define E_ASTR 40
#define E_AS_STAGE (64 * E_ASTR * 4)   // 10240
#define E_BSH_STAGE 10240              // 128*40*2
#define E_AS_BYTES (2 * E_AS_STAGE)    // 20480
#define E_PIPE (E_AS_BYTES + 2 * E_BSH_STAGE)  // 40960

// ---------------- utility kernels ----------------------------------------------
#define PREP_TOTAL (W_TOTAL + 128 * WEH_STRIDE)   // 184320
__global__ void prep_kernel(const float* __restrict__ W1, const float* __restrict__ W2,
                            const float* __restrict__ W3, const float* __restrict__ We,
                            const float* __restrict__ Wm1, const float* __restrict__ Wm2,
                            const float* __restrict__ Wm3) {
    int i = blockIdx.x * blockDim.x + threadIdx.x;
    if (i < 32768) {
        int k = i >> 8, n = i & 255;
        float v = (n < 128) ? W1[k * 128 + n] : W2[k * 128 + (n - 128)];
        g_Wbuf[OFF_NODE + i] = f2tf32(v);
    } else if (i < 65536) {
        g_Wbuf[OFF_M1 + (i - 32768)] = f2tf32(Wm1[i - 32768]);
    } else if (i < 131072) {
        g_Wbuf[OFF_M2 + (i - 65536)] = f2tf32(Wm2[i - 65536]);
    } else if (i < W_TOTAL) {
        g_Wbuf[OFF_M3 + (i - 131072)] = f2tf32(Wm3[i - 131072]);
    } else if (i < PREP_TOTAL) {
        int j = i - W_TOTAL;
        int n = j / WEH_STRIDE, k = j % WEH_STRIDE;
        float v = 0.f;
        if (k < 128)      v = W3[k * 128 + n];
        else if (k < 144) v = We[(k - 128) * 128 + n];
        g_WedgeH[j] = __float2half_rn(v);
    }
}

__global__ void zero_y_stats_kernel() {
    size_t i = (size_t)blockIdx.x * blockDim.x + threadIdx.x;
    const size_t tot = (size_t)N_NODES * HDIM;
    const size_t stride = (size_t)gridDim.x * blockDim.x;
    for (size_t p = i; p < tot; p += stride) g_Y[p] = 0.f;
    if (i < 640) { g_sum[i] = 0.f; g_sq[i] = 0.f; }
}

__global__ void bn_finalize_kernel(const float* __restrict__ g,
                                   const float* __restrict__ b,
                                   int off, int cols, float invCnt) {
    int c = blockIdx.x * blockDim.x + threadIdx.x;
    if (c < cols) {
        float mean = g_sum[off + c] * invCnt;
        float var  = fmaxf(g_sq[off + c] * invCnt - mean * mean, 0.f);
        float a = g[c] * rsqrtf(var + 1e-5f);
        g_scaleArr[off + c] = a;
        g_shiftArr[off + c] = fmaf(-mean, a, b[c]);
    }
}

extern __shared__ char smem_raw[];

// ---------------- 3-stage pipelined tf32 GEMM with fused BN ---------------------
// C[M,NC] = act(A) @ Wu (+cBias); act = relu(aScale[k]*x+aShift[k]) if aScale.
// outHalf: store C as fp16 (PQ output).
__global__ void __launch_bounds__(256, 2) gemm_mma_kernel(
    const float* __restrict__ A, const unsigned* __restrict__ Wu,
    void* __restrict__ Cout, int M, int K, int NC, int outHalf,
    const float* __restrict__ aScale, const float* __restrict__ aShift,
    const float* __restrict__ cBias,
    float* __restrict__ sSum, float* __restrict__ sSq)
{
    float    (*As)[128][36]  = reinterpret_cast<float(*)[128][36]>(smem_raw);
    unsigned (*Bs)[32][136]  = reinterpret_cast<unsigned(*)[32][136]>(smem_raw + G_AS_BYTES);
    float    (*Cs)[132]      = reinterpret_cast<float(*)[132]>(smem_raw);   // overlay
    float* scs  = (float*)(smem_raw + G_PIPE);          // 256
    float* shs  = scs + 256;                            // 256
    float* red0 = shs + 256;                            // 128
    float* red1 = red0 + 128;                           // 128

    const int tid = threadIdx.x, lane = tid & 31, warp = tid >> 5;
    const int wm = (warp & 3) * 32, wn = (warp >> 2) * 64;
    const int bm = blockIdx.y * 128, bn = blockIdx.x * 128;
    const bool useBN = (aScale != nullptr);

    const uint32_t AsAddr = s2u(smem_raw);
    const uint32_t BsAddr = AsAddr + G_AS_BYTES;

    if (useBN && tid < K) { scs[tid] = aScale[tid]; shs[tid] = aShift[tid]; }

    auto issue_copy = [&](int t) {
        const int s = t % 3;
        const int k0 = t * 32;
#pragma unroll
        for (int l = 0; l < 4; l++) {
            int c = tid + l * 256;
            int row = c >> 3, cc = c & 7;
            int grow = bm + row;
            const float* src = A + (size_t)grow * K + k0 + cc * 4;
            uint32_t dst = AsAddr + (uint32_t)(s * G_AS_STAGE + (row * 36 + cc * 4) * 4);
            cp16(dst, src, grow < M);
        }
#pragma unroll
        for (int l = 0; l < 4; l++) {
            int c = tid + l * 256;
            int row = c >> 5, cc = c & 31;
            const unsigned* src = Wu + (size_t)(k0 + row) * NC + bn + cc * 4;
            uint32_t dst = BsAddr + (uint32_t)(s * G_BS_STAGE + (row * 136 + cc * 4) * 4);
            cp16(dst, src, true);
        }
        cp_commit();
    };

    float acc[2][8][4];
#pragma unroll
    for (int mt = 0; mt < 2; mt++)
#pragma unroll
        for (int nt = 0; nt < 8; nt++)
#pragma unroll
            for (int i = 0; i < 4; i++) acc[mt][nt][i] = 0.f;

    const int T = K >> 5;
    issue_copy(0);
    if (T > 1) issue_copy(1);

    for (int t = 0; t < T; t++) {
        if (t + 2 < T)      { issue_copy(t + 2); cp_wait<2>(); }
        else if (t + 1 < T) { cp_wait<1>(); }
        else                { cp_wait<0>(); }
        __syncthreads();
        const int s = t % 3;
        const int k0 = t * 32;
#pragma unroll
        for (int q = 0; q < 4; q++) {
            const int kr = q * 8 + (lane & 3);
            float s0 = 1.f, h0 = 0.f, s4 = 1.f, h4 = 0.f;
            if (useBN) {
                s0 = scs[k0 + kr];     h0 = shs[k0 + kr];
                s4 = scs[k0 + kr + 4]; h4 = shs[k0 + kr + 4];
            }
            unsigned af[2][4], bf[8][2];
#pragma unroll
            for (int mt = 0; mt < 2; mt++) {
                int m = wm + mt * 16 + (lane >> 2);
                float a0 = As[s][m][kr],     a1 = As[s][m + 8][kr];
                float a2 = As[s][m][kr + 4], a3 = As[s][m + 8][kr + 4];
                if (useBN) {
                    a0 = fmaxf(fmaf(a0, s0, h0), 0.f);
                    a1 = fmaxf(fmaf(a1, s0, h0), 0.f);
                    a2 = fmaxf(fmaf(a2, s4, h4), 0.f);
                    a3 = fmaxf(fmaf(a3, s4, h4), 0.f);
                }
                af[mt][0] = f2tf32(a0); af[mt][1] = f2tf32(a1);
                af[mt][2] = f2tf32(a2); af[mt][3] = f2tf32(a3);
            }
#pragma unroll
            for (int nt = 0; nt < 8; nt++) {
                int n = wn + nt * 8 + (lane >> 2);
                bf[nt][0] = Bs[s][kr][n];
                bf[nt][1] = Bs[s][kr + 4][n];
            }
#pragma unroll
            for (int mt = 0; mt < 2; mt++)
#pragma unroll
                for (int nt = 0; nt < 8; nt++)
                    mma_tf32(acc[mt][nt], af[mt], bf[nt]);
        }
        __syncthreads();
    }

    // ---------------- epilogue: stage -> smem, warp-per-row coalesced ----------
#pragma unroll
    for (int mt = 0; mt < 2; mt++)
#pragma unroll
        for (int half = 0; half < 2; half++) {
            int r = wm + mt * 16 + (lane >> 2) + half * 8;
#pragma unroll
            for (int nt = 0; nt < 8; nt++) {
                int cl = wn + nt * 8 + 2 * (lane & 3);
                float2 v; v.x = acc[mt][nt][half * 2 + 0]; v.y = acc[mt][nt][half * 2 + 1];
                *(float2*)&Cs[r][cl] = v;
            }
        }
    if (sSum && tid < 128) { red0[tid] = 0.f; red1[tid] = 0.f; }
    __syncthreads();

    float4 bias = make_float4(0.f, 0.f, 0.f, 0.f);
    if (cBias) bias = *(const float4*)(cBias + bn + lane * 4);
    float psum[4] = {0.f, 0.f, 0.f, 0.f}, psq[4] = {0.f, 0.f, 0.f, 0.f};

#pragma unroll
    for (int i = 0; i < 16; i++) {
        int r = warp * 16 + i;
        int R = bm + r;
        if (R < M) {
            float4 v = *(const float4*)&Cs[r][lane * 4];
            v.x += bias.x; v.y += bias.y; v.z += bias.z; v.w += bias.w;
            if (outHalf) {
                __half* Ch = (__half*)Cout;
                *(uint2*)(Ch + (size_t)R * NC + bn + lane * 4) = pack_half4(v);
            } else {
                float* Cf = (float*)Cout;
                *(float4*)(Cf + (size_t)R * NC + bn + lane * 4) = v;
            }
            psum[0] += v.x; psum[1] += v.y; psum[2] += v.z; psum[3] += v.w;
            psq[0] += v.x * v.x; psq[1] += v.y * v.y;
            psq[2] += v.z * v.z; psq[3] += v.w * v.w;
        }
    }

    if (sSum) {
        __syncthreads();
#pragma unroll
        for (int j = 0; j < 4; j++) {
            atomicAdd(&red0[lane * 4 + j], psum[j]);
            atomicAdd(&red1[lane * 4 + j], psq[j]);
        }
        __syncthreads();
        if (tid < 128) {
            atomicAdd(&sSum[bn + tid], red0[tid]);
            atomicAdd(&sSq [bn + tid], red1[tid]);
        }
    }
}

// ---------------- edge message kernel: fp16 HMMA m16n8k16 ----------------------
// MSG[e] = edge_rep[e]@W3 + edge_attr[e]@We + be + P[src[e]] + Q[dst[e]], + stats
// A: fp32 in smem (64x40, conflict-free), converted to half2 at fragment load.
// B: fp16 [n][k] in smem (128x40, conflict-free), from g_WedgeH.
__global__ void __launch_bounds__(256, 3) edge_msg_kernel(
    const float* __restrict__ edge_rep, const float* __restrict__ edge_attr,
    const int* __restrict__ src, const int* __restrict__ dst,
    const float* __restrict__ be)
{
    float  (*As)[64][E_ASTR] = reinterpret_cast<float(*)[64][E_ASTR]>(smem_raw);
    __half (*Bs)[128][40]    = reinterpret_cast<__half(*)[128][40]>(smem_raw + E_AS_BYTES);
    float  (*Cs)[132]        = reinterpret_cast<float(*)[132]>(smem_raw);   // overlay
    float* red0 = (float*)(smem_raw + E_PIPE);
    float* red1 = red0 + 128;

    const int tid = threadIdx.x, lane = tid & 31, warp = tid >> 5;
    const int wm = (warp & 1) * 32, wn = (warp >> 1) * 32;
    const int g  = lane >> 2;
    const int c2 = (lane & 3) * 2;
    const size_t bm = (size_t)blockIdx.x * 64;

    const uint32_t AsAddr = s2u(smem_raw);
    const uint32_t BsAddr = AsAddr + E_AS_BYTES;

    // L2 prefetch of the P/Q gather rows (hidden behind mainloop)
    if (tid < 128) {
        int e0 = (int)bm + (tid >> 1);
        const __half* row = (tid & 1) ? (g_PQh + (size_t)dst[e0] * 256 + 128)
                                      : (g_PQh + (size_t)src[e0] * 256);
        asm volatile("prefetch.global.L2 [%0];" :: "l"(row));
        asm volatile("prefetch.global.L2 [%0];" :: "l"(row + 64));
    }

    auto issue_copy = [&](int t) {
        const int s = t & 1;
        if (t < 4) {
            const int k0 = t * 32;
            // A: 64 rows x 32 floats = 512 chunks / 256 thr = 2
#pragma unroll
            for (int l = 0; l < 2; l++) {
                int c = tid + l * 256;
                int row = c >> 3, cc = c & 7;
                const float* sp = edge_rep + (bm + row) * HDIM + k0 + cc * 4;
                uint32_t dp = AsAddr + (uint32_t)(s * E_AS_STAGE + (row * E_ASTR + cc * 4) * 4);
                cp16(dp, sp, true);
            }
            // B: 128 rows x 32 halfs = 512 chunks(16B=8h) / 256 thr = 2
#pragma unroll
            for (int l = 0; l < 2; l++) {
                int c = tid + l * 256;
                int row = c >> 2, cc = c & 3;
                const __half* sp = g_WedgeH + (size_t)row * WEH_STRIDE + k0 + cc * 8;
                uint32_t dp = BsAddr + (uint32_t)(s * E_BSH_STAGE + (row * 40 + cc * 8) * 2);
                cp16(dp, sp, true);
            }
        } else {
            // tail K=16: A = edge_attr (64 rows x 16 floats = 256 chunks)
            {
                int row = tid >> 2, cc = tid & 3;
                const float* sp = edge_attr + (bm + row) * EDIM + cc * 4;
                uint32_t dp = AsAddr + (uint32_t)(s * E_AS_STAGE + (row * E_ASTR + cc * 4) * 4);
                cp16(dp, sp, true);
            }
            // B tail: 128 rows x 16 halfs = 256 chunks
            {
                int row = tid >> 1, cc = tid & 1;
                const __half* sp = g_WedgeH + (size_t)row * WEH_STRIDE + 128 + cc * 8;
                uint32_t dp = BsAddr + (uint32_t)(s * E_BSH_STAGE + (row * 40 + cc * 8) * 2);
                cp16(dp, sp, true);
            }
        }
        cp_commit();
    };

    float acc[2][4][4];
#pragma unroll
    for (int mt = 0; mt < 2; mt++)
#pragma unroll
        for (int nt = 0; nt < 4; nt++)
#pragma unroll
            for (int i = 0; i < 4; i++) acc[mt][nt][i] = 0.f;

    issue_copy(0);

#pragma unroll
    for (int t = 0; t < 5; t++) {
        cp_wait<0>();
        __syncthreads();
        if (t + 1 < 5) issue_copy(t + 1);
        const int s = t & 1;
        const int ksteps = (t < 4) ? 2 : 1;
#pragma unroll
        for (int ks = 0; ks < 2; ks++) {
            if (ks >= ksteps) break;
            const int kk = ks * 16;
            unsigned af[2][4], bf[4][2];
#pragma unroll
            for (int mt = 0; mt < 2; mt++) {
                int m = wm + mt * 16 + g;
                af[mt][0] = h2_from_f2(*(const float2*)&As[s][m    ][kk + c2]);
                af[mt][1] = h2_from_f2(*(const float2*)&As[s][m + 8][kk + c2]);
                af[mt][2] = h2_from_f2(*(const float2*)&As[s][m    ][kk + c2 + 8]);
                af[mt][3] = h2_from_f2(*(const float2*)&As[s][m + 8][kk + c2 + 8]);
            }
#pragma unroll
            for (int nt = 0; nt < 4; nt++) {
                int n = wn + nt * 8 + g;
                bf[nt][0] = *(const unsigned*)&Bs[s][n][kk + c2];
                bf[nt][1] = *(const unsigned*)&Bs[s][n][kk + c2 + 8];
            }
#pragma unroll
            for (int mt = 0; mt < 2; mt++)
#pragma unroll
                for (int nt = 0; nt < 4; nt++)
                    mma_f16(acc[mt][nt], af[mt], bf[nt]);
        }
        __syncthreads();
    }

    // ---------------- epilogue: stage -> smem, warp-per-edge coalesced ---------
#pragma unroll
    for (int mt = 0; mt < 2; mt++)
#pragma unroll
        for (int half = 0; half < 2; half++) {
            int r = wm + mt * 16 + g + half * 8;
#pragma unroll
            for (int nt = 0; nt < 4; nt++) {
                int cl = wn + nt * 8 + c2;
                float2 v; v.x = acc[mt][nt][half * 2 + 0]; v.y = acc[mt][nt][half * 2 + 1];
                *(float2*)&Cs[r][cl] = v;
            }
        }
    if (tid < 128) { red0[tid] = 0.f; red1[tid] = 0.f; }
    __syncthreads();

    float4 bev = *(const float4*)(be + lane * 4);
    float psum[4] = {0.f, 0.f, 0.f, 0.f}, psq[4] = {0.f, 0.f, 0.f, 0.f};

#pragma unroll
    for (int i = 0; i < 8; i++) {
        int r = warp * 8 + i;
        size_t e = bm + r;
        int s = src[e], d = dst[e];
        float4 pv = unpack_half4(*(const uint2*)(g_PQh + (size_t)s * 256 + lane * 4));
        float4 qv = unpack_half4(*(const uint2*)(g_PQh + (size_t)d * 256 + 128 + lane * 4));
        float4 v = *(const float4*)&Cs[r][lane * 4];
        v.x += pv.x + qv.x + bev.x;
        v.y += pv.y + qv.y + bev.y;
        v.z += pv.z + qv.z + bev.z;
        v.w += pv.w + qv.w + bev.w;
        *(uint2*)(g_MSGh + e * HDIM + lane * 4) = pack_half4(v);
        psum[0] += v.x; psum[1] += v.y; psum[2] += v.z; psum[3] += v.w;
        psq[0] += v.x * v.x; psq[1] += v.y * v.y;
        psq[2] += v.z * v.z; psq[3] += v.w * v.w;
    }

    __syncthreads();
#pragma unroll
    for (int j = 0; j < 4; j++) {
        atomicAdd(&red0[lane * 4 + j], psum[j]);
        atomicAdd(&red1[lane * 4 + j], psq[j]);
    }
    __syncthreads();
    if (tid < 128) {
        atomicAdd(&g_sum[tid], red0[tid]);
        atomicAdd(&g_sq [tid], red1[tid]);
    }
}

// ---------------- BN+ReLU+scatter with vector red ------------------------------
__global__ void scatter_kernel(const int* __restrict__ dst) {
    unsigned t = blockIdx.x * blockDim.x + threadIdx.x;
    size_t e = (size_t)(t >> 5);
    int c4 = (t & 31) * 4;
    if (e < (size_t)N_EDGES) {
        int d = dst[e];
        float4 m = unpack_half4(*(const uint2*)(g_MSGh + e * HDIM + c4));
        float v0 = fmaxf(fmaf(m.x, g_scaleArr[c4 + 0], g_shiftArr[c4 + 0]), 0.f);
        float v1 = fmaxf(fmaf(m.y, g_scaleArr[c4 + 1], g_shiftArr[c4 + 1]), 0.f);
        float v2 = fmaxf(fmaf(m.z, g_scaleArr[c4 + 2], g_shiftArr[c4 + 2]), 0.f);
        float v3 = fmaxf(fmaf(m.w, g_scaleArr[c4 + 3], g_shiftArr[c4 + 3]), 0.f);
        float* p = g_Y + (size_t)d * HDIM + c4;
        asm volatile("red.global.add.v4.f32 [%0], {%1,%2,%3,%4};"
                     :: "l"(p), "f"(v0), "f"(v1), "f"(v2), "f"(v3) : "memory");
    }
}

// ---------------- launch ------------------------------------------------------
extern "C" void kernel_launch(void* const* d_in, const int* in_sizes, int n_in,
                              void* d_out, int out_size) {
    const float* node_rep  = (const float*)d_in[0];
    const float* edge_rep  = (const float*)d_in[1];
    const float* edge_attr = (const float*)d_in[2];
    const int*   eidx      = (const int*)d_in[3];
    const float* W1  = (const float*)d_in[4];
    const float* W2  = (const float*)d_in[5];
    const float* W3  = (const float*)d_in[6];
    const float* We  = (const float*)d_in[7];
    const float* be  = (const float*)d_in[8];
    const float* bng = (const float*)d_in[9];
    const float* bnb = (const float*)d_in[10];
    const float* Wm1 = (const float*)d_in[11];
    const float* g1  = (const float*)d_in[12];
    const float* b1  = (const float*)d_in[13];
    const float* Wm2 = (const float*)d_in[14];
    const float* g2  = (const float*)d_in[15];
    const float* b2  = (const float*)d_in[16];
    const float* Wm3 = (const float*)d_in[17];
    const float* bm3 = (const float*)d_in[18];
    float* out = (float*)d_out;

    const int* src = eidx;
    const int* dst = eidx + N_EDGES;

    float *Y, *H1, *H2, *SUM, *SQ, *SCALE, *SHIFT;
    __half* PQh;
    unsigned* WB;
    cudaGetSymbolAddress((void**)&PQh, g_PQh);
    cudaGetSymbolAddress((void**)&Y,  g_Y);
    cudaGetSymbolAddress((void**)&H1, g_H1);
    cudaGetSymbolAddress((void**)&H2, g_H2);
    cudaGetSymbolAddress((void**)&SUM,   g_sum);
    cudaGetSymbolAddress((void**)&SQ,    g_sq);
    cudaGetSymbolAddress((void**)&SCALE, g_scaleArr);
    cudaGetSymbolAddress((void**)&SHIFT, g_shiftArr);
    cudaGetSymbolAddress((void**)&WB, g_Wbuf);

    const int GEMM_SMEM = G_PIPE + 2048 + 1024;   // 110592
    const int EDGE_SMEM = E_PIPE + 1024;          // 41984
    cudaFuncSetAttribute(gemm_mma_kernel, cudaFuncAttributeMaxDynamicSharedMemorySize, GEMM_SMEM);
    cudaFuncSetAttribute(edge_msg_kernel, cudaFuncAttributeMaxDynamicSharedMemorySize, EDGE_SMEM);

    const int MBLK = (N_NODES + 127) / 128;  // 782

    prep_kernel<<<(PREP_TOTAL + 255) / 256, 256>>>(W1, W2, W3, We, Wm1, Wm2, Wm3);
    zero_y_stats_kernel<<<4096, 256>>>();

    // fused node linears: PQ = node_rep @ [W1|W2] -> fp16
    gemm_mma_kernel<<<dim3(2, MBLK), 256, GEMM_SMEM>>>(
        node_rep, WB + OFF_NODE, PQh, N_NODES, HDIM, 256, 1,
        nullptr, nullptr, nullptr, nullptr, nullptr);

    // edge GEMM (fp16 HMMA, conflict-free smem) + encoder + gathers + BN stats
    edge_msg_kernel<<<N_EDGES / 64, 256, EDGE_SMEM>>>(edge_rep, edge_attr, src, dst, be);

    bn_finalize_kernel<<<1, 128>>>(bng, bnb, 0, 128, 1.f / (float)N_EDGES);

    // BN + ReLU + scatter-sum
    scatter_kernel<<<(N_EDGES * 32) / 256, 256>>>(dst);

    // MLP layer 1: H1(fp32) = Y @ Wm1
    gemm_mma_kernel<<<dim3(2, MBLK), 256, GEMM_SMEM>>>(
        Y, WB + OFF_M1, H1, N_NODES, HDIM, H2DIM, 0,
        nullptr, nullptr, nullptr, SUM + 128, SQ + 128);
    bn_finalize_kernel<<<2, 128>>>(g1, b1, 128, 256, 1.f / (float)N_NODES);

    // MLP layer 2: H2(fp32) = relu(bn1(H1)) @ Wm2
    gemm_mma_kernel<<<dim3(2, MBLK), 256, GEMM_SMEM>>>(
        H1, WB + OFF_M2, H2, N_NODES, H2DIM, H2DIM, 0,
        SCALE + 128, SHIFT + 128, nullptr, SUM + 384, SQ + 384);
    bn_finalize_kernel<<<2, 128>>>(g2, b2, 384, 256, 1.f / (float)N_NODES);

    // MLP layer 3: out = relu(bn2(H2)) @ Wm3 + bm3
    gemm_mma_kernel<<<dim3(1, MBLK), 256, GEMM_SMEM>>>(
        H2, WB + OFF_M3, out, N_NODES, H2DIM, HDIM, 0,
        SCALE + 384, SHIFT + 384, bm3, nullptr, nullptr);
}

// round 13
// speedup vs baseline: 1.1751x; 1.1409x over previous
#include <cuda_runtime.h>
#include <cuda_fp16.h>
#include <cstdint>

#define N_NODES 100000
#define N_EDGES 640000
#define HDIM 128
#define H2DIM 256
#define EDIM 16

// ---------------- scratch (device globals) ------------------------------------
__device__ __half g_PQh [(size_t)N_NODES * 256];   // fp16: [0:128]=node@W1, [128:256]=node@W2
__device__ __half g_MSGh[(size_t)N_EDGES * HDIM];  // fp16 pre-BN messages
__device__ float  g_Y   [(size_t)N_NODES * HDIM];  // scatter target (fp32 accum)
__device__ float  g_H1  [(size_t)N_NODES * H2DIM]; // fp32 MLP intermediates (error budget)
__device__ float  g_H2  [(size_t)N_NODES * H2DIM];
// BN stat slots: [0,128)=msg, [128,384)=bn1, [384,640)=bn2
__device__ float g_sum[640];
__device__ float g_sq [640];
__device__ float g_scaleArr[640];
__device__ float g_shiftArr[640];

// fp16 weights in [n][k] layout for HMMA (B operand = col-major)
#define OFF_NODE 0        // [256 n][128 k]  W1 | W2
#define OFF_M1   32768    // [256 n][128 k]
#define OFF_M2   65536    // [256 n][256 k]
#define OFF_M3   131072   // [128 n][256 k]
#define WH_TOTAL 163840
__device__ __half g_WallH[WH_TOTAL];
// edge weights fp16 [n][k]: k 0..127 = W3, 128..143 = We, stride 160
#define WEH_STRIDE 160
__device__ __half g_WedgeH[128 * WEH_STRIDE];

// ---------------- helpers ------------------------------------------------------
__device__ __forceinline__ void mma_f16(float* c, const unsigned* a, const unsigned* b) {
    asm volatile(
        "mma.sync.aligned.m16n8k16.row.col.f32.f16.f16.f32 "
        "{%0,%1,%2,%3}, {%4,%5,%6,%7}, {%8,%9}, {%0,%1,%2,%3};"
        : "+f"(c[0]), "+f"(c[1]), "+f"(c[2]), "+f"(c[3])
        : "r"(a[0]), "r"(a[1]), "r"(a[2]), "r"(a[3]), "r"(b[0]), "r"(b[1]));
}

__device__ __forceinline__ void cp16(uint32_t dst, const void* src, bool pred) {
    int sz = pred ? 16 : 0;
    asm volatile("cp.async.cg.shared.global [%0], [%1], 16, %2;"
                 :: "r"(dst), "l"(src), "r"(sz));
}
__device__ __forceinline__ void cp_commit() { asm volatile("cp.async.commit_group;"); }
template <int N> __device__ __forceinline__ void cp_wait() {
    asm volatile("cp.async.wait_group %0;" :: "n"(N));
}
__device__ __forceinline__ uint32_t s2u(const void* p) {
    uint32_t a;
    asm("{ .reg .u64 t; cvta.to.shared.u64 t, %1; cvt.u32.u64 %0, t; }" : "=r"(a) : "l"(p));
    return a;
}
__device__ __forceinline__ uint2 pack_half4(float4 v) {
    __half2 h0 = __floats2half2_rn(v.x, v.y);
    __half2 h1 = __floats2half2_rn(v.z, v.w);
    uint2 u;
    u.x = *(unsigned*)&h0;
    u.y = *(unsigned*)&h1;
    return u;
}
__device__ __forceinline__ float4 unpack_half4(uint2 u) {
    __half2 h0 = *(__half2*)&u.x;
    __half2 h1 = *(__half2*)&u.y;
    float2 f0 = __half22float2(h0);
    float2 f1 = __half22float2(h1);
    return make_float4(f0.x, f0.y, f1.x, f1.y);
}
__device__ __forceinline__ unsigned h2_from_f2(float2 f) {
    __half2 h = __float22half2_rn(f);
    return *(unsigned*)&h;
}

// dense GEMM smem: A 128x40 fp32, B 128x40 fp16, 3 stages (conflict-free)
#define G_ASTR 40
#define G_AS_STAGE (128 * G_ASTR * 4)   // 20480
#define G_BSH_STAGE (128 * 40 * 2)      // 10240
#define G_AS_BYTES (3 * G_AS_STAGE)     // 61440
#define G_BS_BYTES (3 * G_BSH_STAGE)    // 30720
#define G_PIPE (G_AS_BYTES + G_BS_BYTES)  // 92160
// edge smem: A 64x40 fp32, B 128x40 fp16, 2 stages
#define E_ASTR 40
#define E_AS_STAGE (64 * E_ASTR * 4)   // 10240
#define E_BSH_STAGE 10240              // 128*40*2
#define E_AS_BYTES (2 * E_AS_STAGE)    // 20480
#define E_PIPE (E_AS_BYTES + 2 * E_BSH_STAGE)  // 40960

// ---------------- utility kernels ----------------------------------------------
#define PREP_TOTAL (WH_TOTAL + 128 * WEH_STRIDE)   // 184320
__global__ void prep_kernel(const float* __restrict__ W1, const float* __restrict__ W2,
                            const float* __restrict__ W3, const float* __restrict__ We,
                            const float* __restrict__ Wm1, const float* __restrict__ Wm2,
                            const float* __restrict__ Wm3) {
    int i = blockIdx.x * blockDim.x + threadIdx.x;
    if (i < 32768) {
        int n = i >> 7, k = i & 127;
        float v = (n < 128) ? W1[k * 128 + n] : W2[k * 128 + (n - 128)];
        g_WallH[OFF_NODE + i] = __float2half_rn(v);
    } else if (i < 65536) {
        int j = i - 32768;
        int n = j >> 7, k = j & 127;
        g_WallH[OFF_M1 + j] = __float2half_rn(Wm1[k * 256 + n]);
    } else if (i < 131072) {
        int j = i - 65536;
        int n = j >> 8, k = j & 255;
        g_WallH[OFF_M2 + j] = __float2half_rn(Wm2[k * 256 + n]);
    } else if (i < WH_TOTAL) {
        int j = i - 131072;
        int n = j >> 8, k = j & 255;
        g_WallH[OFF_M3 + j] = __float2half_rn(Wm3[k * 128 + n]);
    } else if (i < PREP_TOTAL) {
        int j = i - WH_TOTAL;
        int n = j / WEH_STRIDE, k = j % WEH_STRIDE;
        float v = 0.f;
        if (k < 128)      v = W3[k * 128 + n];
        else if (k < 144) v = We[(k - 128) * 128 + n];
        g_WedgeH[j] = __float2half_rn(v);
    }
}

__global__ void zero_y_stats_kernel() {
    size_t i = (size_t)blockIdx.x * blockDim.x + threadIdx.x;
    const size_t tot = (size_t)N_NODES * HDIM;
    const size_t stride = (size_t)gridDim.x * blockDim.x;
    for (size_t p = i; p < tot; p += stride) g_Y[p] = 0.f;
    if (i < 640) { g_sum[i] = 0.f; g_sq[i] = 0.f; }
}

__global__ void bn_finalize_kernel(const float* __restrict__ g,
                                   const float* __restrict__ b,
                                   int off, int cols, float invCnt) {
    int c = blockIdx.x * blockDim.x + threadIdx.x;
    if (c < cols) {
        float mean = g_sum[off + c] * invCnt;
        float var  = fmaxf(g_sq[off + c] * invCnt - mean * mean, 0.f);
        float a = g[c] * rsqrtf(var + 1e-5f);
        g_scaleArr[off + c] = a;
        g_shiftArr[off + c] = fmaf(-mean, a, b[c]);
    }
}

extern __shared__ char smem_raw[];

// ---------------- 3-stage pipelined fp16-HMMA GEMM with fused BN ----------------
// C[M,NC] = act(A) @ Wh^T (+cBias); Wh is fp16 [n][k], act applied in fp32.
// Warp tile 32x64, HMMA m16n8k16 (2 k-steps per 32-k tile). outHalf: fp16 C.
__global__ void __launch_bounds__(256, 2) gemm_mma_kernel(
    const float* __restrict__ A, const __half* __restrict__ Wh, int KSTR,
    void* __restrict__ Cout, int M, int K, int NC, int outHalf,
    const float* __restrict__ aScale, const float* __restrict__ aShift,
    const float* __restrict__ cBias,
    float* __restrict__ sSum, float* __restrict__ sSq)
{
    float  (*As)[128][G_ASTR] = reinterpret_cast<float(*)[128][G_ASTR]>(smem_raw);
    __half (*Bs)[128][40]     = reinterpret_cast<__half(*)[128][40]>(smem_raw + G_AS_BYTES);
    float  (*Cs)[132]         = reinterpret_cast<float(*)[132]>(smem_raw);   // overlay
    float* scs  = (float*)(smem_raw + G_PIPE);          // 256
    float* shs  = scs + 256;                            // 256
    float* red0 = shs + 256;                            // 128
    float* red1 = red0 + 128;                           // 128

    const int tid = threadIdx.x, lane = tid & 31, warp = tid >> 5;
    const int wm = (warp & 3) * 32, wn = (warp >> 2) * 64;
    const int g  = lane >> 2;
    const int c2 = (lane & 3) * 2;
    const int bm = blockIdx.y * 128, bn = blockIdx.x * 128;
    const bool useBN = (aScale != nullptr);

    const uint32_t AsAddr = s2u(smem_raw);
    const uint32_t BsAddr = AsAddr + G_AS_BYTES;

    if (useBN && tid < K) { scs[tid] = aScale[tid]; shs[tid] = aShift[tid]; }

    auto issue_copy = [&](int t) {
        const int s = t % 3;
        const int k0 = t * 32;
        // A: 128 rows x 32 floats = 1024 16B-chunks / 256 thr = 4
#pragma unroll
        for (int l = 0; l < 4; l++) {
            int c = tid + l * 256;
            int row = c >> 3, cc = c & 7;
            int grow = bm + row;
            const float* src = A + (size_t)grow * K + k0 + cc * 4;
            uint32_t dst = AsAddr + (uint32_t)(s * G_AS_STAGE + (row * G_ASTR + cc * 4) * 4);
            cp16(dst, src, grow < M);
        }
        // B: 128 n-rows x 32 halfs = 512 chunks / 256 thr = 2
#pragma unroll
        for (int l = 0; l < 2; l++) {
            int c = tid + l * 256;
            int row = c >> 2, cc = c & 3;
            const __half* src = Wh + (size_t)(bn + row) * KSTR + k0 + cc * 8;
            uint32_t dst = BsAddr + (uint32_t)(s * G_BSH_STAGE + (row * 40 + cc * 8) * 2);
            cp16(dst, src, true);
        }
        cp_commit();
    };

    float acc[2][8][4];
#pragma unroll
    for (int mt = 0; mt < 2; mt++)
#pragma unroll
        for (int nt = 0; nt < 8; nt++)
#pragma unroll
            for (int i = 0; i < 4; i++) acc[mt][nt][i] = 0.f;

    const int T = K >> 5;
    issue_copy(0);
    if (T > 1) issue_copy(1);

    for (int t = 0; t < T; t++) {
        if (t + 2 < T)      { issue_copy(t + 2); cp_wait<2>(); }
        else if (t + 1 < T) { cp_wait<1>(); }
        else                { cp_wait<0>(); }
        __syncthreads();
        const int s = t % 3;
        const int k0 = t * 32;
#pragma unroll
        for (int ks = 0; ks < 2; ks++) {
            const int kk = ks * 16;
            float2 scLo = make_float2(1.f, 1.f), shLo = make_float2(0.f, 0.f);
            float2 scHi = make_float2(1.f, 1.f), shHi = make_float2(0.f, 0.f);
            if (useBN) {
                scLo = *(const float2*)&scs[k0 + kk + c2];
                shLo = *(const float2*)&shs[k0 + kk + c2];
                scHi = *(const float2*)&scs[k0 + kk + c2 + 8];
                shHi = *(const float2*)&shs[k0 + kk + c2 + 8];
            }
            unsigned af[2][4], bf[8][2];
#pragma unroll
            for (int mt = 0; mt < 2; mt++) {
                int m = wm + mt * 16 + g;
                float2 a0 = *(const float2*)&As[s][m    ][kk + c2];
                float2 a1 = *(const float2*)&As[s][m + 8][kk + c2];
                float2 a2 = *(const float2*)&As[s][m    ][kk + c2 + 8];
                float2 a3 = *(const float2*)&As[s][m + 8][kk + c2 + 8];
                if (useBN) {
                    a0.x = fmaxf(fmaf(a0.x, scLo.x, shLo.x), 0.f);
                    a0.y = fmaxf(fmaf(a0.y, scLo.y, shLo.y), 0.f);
                    a1.x = fmaxf(fmaf(a1.x, scLo.x, shLo.x), 0.f);
                    a1.y = fmaxf(fmaf(a1.y, scLo.y, shLo.y), 0.f);
                    a2.x = fmaxf(fmaf(a2.x, scHi.x, shHi.x), 0.f);
                    a2.y = fmaxf(fmaf(a2.y, scHi.y, shHi.y), 0.f);
                    a3.x = fmaxf(fmaf(a3.x, scHi.x, shHi.x), 0.f);
                    a3.y = fmaxf(fmaf(a3.y, scHi.y, shHi.y), 0.f);
                }
                af[mt][0] = h2_from_f2(a0);
                af[mt][1] = h2_from_f2(a1);
                af[mt][2] = h2_from_f2(a2);
                af[mt][3] = h2_from_f2(a3);
            }
#pragma unroll
            for (int nt = 0; nt < 8; nt++) {
                int n = wn + nt * 8 + g;
                bf[nt][0] = *(const unsigned*)&Bs[s][n][kk + c2];
                bf[nt][1] = *(const unsigned*)&Bs[s][n][kk + c2 + 8];
            }
#pragma unroll
            for (int mt = 0; mt < 2; mt++)
#pragma unroll
                for (int nt = 0; nt < 8; nt++)
                    mma_f16(acc[mt][nt], af[mt], bf[nt]);
        }
        __syncthreads();
    }

    // ---------------- epilogue: stage -> smem, warp-per-row coalesced ----------
#pragma unroll
    for (int mt = 0; mt < 2; mt++)
#pragma unroll
        for (int half = 0; half < 2; half++) {
            int r = wm + mt * 16 + g + half * 8;
#pragma unroll
            for (int nt = 0; nt < 8; nt++) {
                int cl = wn + nt * 8 + c2;
                float2 v; v.x = acc[mt][nt][half * 2 + 0]; v.y = acc[mt][nt][half * 2 + 1];
                *(float2*)&Cs[r][cl] = v;
            }
        }
    if (sSum && tid < 128) { red0[tid] = 0.f; red1[tid] = 0.f; }
    __syncthreads();

    float4 bias = make_float4(0.f, 0.f, 0.f, 0.f);
    if (cBias) bias = *(const float4*)(cBias + bn + lane * 4);
    float psum[4] = {0.f, 0.f, 0.f, 0.f}, psq[4] = {0.f, 0.f, 0.f, 0.f};

#pragma unroll
    for (int i = 0; i < 16; i++) {
        int r = warp * 16 + i;
        int R = bm + r;
        if (R < M) {
            float4 v = *(const float4*)&Cs[r][lane * 4];
            v.x += bias.x; v.y += bias.y; v.z += bias.z; v.w += bias.w;
            if (outHalf) {
                __half* Ch = (__half*)Cout;
                *(uint2*)(Ch + (size_t)R * NC + bn + lane * 4) = pack_half4(v);
            } else {
                float* Cf = (float*)Cout;
                *(float4*)(Cf + (size_t)R * NC + bn + lane * 4) = v;
            }
            psum[0] += v.x; psum[1] += v.y; psum[2] += v.z; psum[3] += v.w;
            psq[0] += v.x * v.x; psq[1] += v.y * v.y;
            psq[2] += v.z * v.z; psq[3] += v.w * v.w;
        }
    }

    if (sSum) {
        __syncthreads();
#pragma unroll
        for (int j = 0; j < 4; j++) {
            atomicAdd(&red0[lane * 4 + j], psum[j]);
            atomicAdd(&red1[lane * 4 + j], psq[j]);
        }
        __syncthreads();
        if (tid < 128) {
            atomicAdd(&sSum[bn + tid], red0[tid]);
            atomicAdd(&sSq [bn + tid], red1[tid]);
        }
    }
}

// ---------------- edge message kernel: fp16 HMMA (R12, unchanged) ---------------
__global__ void __launch_bounds__(256, 3) edge_msg_kernel(
    const float* __restrict__ edge_rep, const float* __restrict__ edge_attr,
    const int* __restrict__ src, const int* __restrict__ dst,
    const float* __restrict__ be)
{
    float  (*As)[64][E_ASTR] = reinterpret_cast<float(*)[64][E_ASTR]>(smem_raw);
    __half (*Bs)[128][40]    = reinterpret_cast<__half(*)[128][40]>(smem_raw + E_AS_BYTES);
    float  (*Cs)[132]        = reinterpret_cast<float(*)[132]>(smem_raw);   // overlay
    float* red0 = (float*)(smem_raw + E_PIPE);
    float* red1 = red0 + 128;

    const int tid = threadIdx.x, lane = tid & 31, warp = tid >> 5;
    const int wm = (warp & 1) * 32, wn = (warp >> 1) * 32;
    const int g  = lane >> 2;
    const int c2 = (lane & 3) * 2;
    const size_t bm = (size_t)blockIdx.x * 64;

    const uint32_t AsAddr = s2u(smem_raw);
    const uint32_t BsAddr = AsAddr + E_AS_BYTES;

    if (tid < 128) {
        int e0 = (int)bm + (tid >> 1);
        const __half* row = (tid & 1) ? (g_PQh + (size_t)dst[e0] * 256 + 128)
                                      : (g_PQh + (size_t)src[e0] * 256);
        asm volatile("prefetch.global.L2 [%0];" :: "l"(row));
        asm volatile("prefetch.global.L2 [%0];" :: "l"(row + 64));
    }

    auto issue_copy = [&](int t) {
        const int s = t & 1;
        if (t < 4) {
            const int k0 = t * 32;
#pragma unroll
            for (int l = 0; l < 2; l++) {
                int c = tid + l * 256;
                int row = c >> 3, cc = c & 7;
                const float* sp = edge_rep + (bm + row) * HDIM + k0 + cc * 4;
                uint32_t dp = AsAddr + (uint32_t)(s * E_AS_STAGE + (row * E_ASTR + cc * 4) * 4);
                cp16(dp, sp, true);
            }
#pragma unroll
            for (int l = 0; l < 2; l++) {
                int c = tid + l * 256;
                int row = c >> 2, cc = c & 3;
                const __half* sp = g_WedgeH + (size_t)row * WEH_STRIDE + k0 + cc * 8;
                uint32_t dp = BsAddr + (uint32_t)(s * E_BSH_STAGE + (row * 40 + cc * 8) * 2);
                cp16(dp, sp, true);
            }
        } else {
            {
                int row = tid >> 2, cc = tid & 3;
                const float* sp = edge_attr + (bm + row) * EDIM + cc * 4;
                uint32_t dp = AsAddr + (uint32_t)(s * E_AS_STAGE + (row * E_ASTR + cc * 4) * 4);
                cp16(dp, sp, true);
            }
            {
                int row = tid >> 1, cc = tid & 1;
                const __half* sp = g_WedgeH + (size_t)row * WEH_STRIDE + 128 + cc * 8;
                uint32_t dp = BsAddr + (uint32_t)(s * E_BSH_STAGE + (row * 40 + cc * 8) * 2);
                cp16(dp, sp, true);
            }
        }
        cp_commit();
    };

    float acc[2][4][4];
#pragma unroll
    for (int mt = 0; mt < 2; mt++)
#pragma unroll
        for (int nt = 0; nt < 4; nt++)
#pragma unroll
            for (int i = 0; i < 4; i++) acc[mt][nt][i] = 0.f;

    issue_copy(0);

#pragma unroll
    for (int t = 0; t < 5; t++) {
        cp_wait<0>();
        __syncthreads();
        if (t + 1 < 5) issue_copy(t + 1);
        const int s = t & 1;
        const int ksteps = (t < 4) ? 2 : 1;
#pragma unroll
        for (int ks = 0; ks < 2; ks++) {
            if (ks >= ksteps) break;
            const int kk = ks * 16;
            unsigned af[2][4], bf[4][2];
#pragma unroll
            for (int mt = 0; mt < 2; mt++) {
                int m = wm + mt * 16 + g;
                af[mt][0] = h2_from_f2(*(const float2*)&As[s][m    ][kk + c2]);
                af[mt][1] = h2_from_f2(*(const float2*)&As[s][m + 8][kk + c2]);
                af[mt][2] = h2_from_f2(*(const float2*)&As[s][m    ][kk + c2 + 8]);
                af[mt][3] = h2_from_f2(*(const float2*)&As[s][m + 8][kk + c2 + 8]);
            }
#pragma unroll
            for (int nt = 0; nt < 4; nt++) {
                int n = wn + nt * 8 + g;
                bf[nt][0] = *(const unsigned*)&Bs[s][n][kk + c2];
                bf[nt][1] = *(const unsigned*)&Bs[s][n][kk + c2 + 8];
            }
#pragma unroll
            for (int mt = 0; mt < 2; mt++)
#pragma unroll
                for (int nt = 0; nt < 4; nt++)
                    mma_f16(acc[mt][nt], af[mt], bf[nt]);
        }
        __syncthreads();
    }

#pragma unroll
    for (int mt = 0; mt < 2; mt++)
#pragma unroll
        for (int half = 0; half < 2; half++) {
            int r = wm + mt * 16 + g + half * 8;
#pragma unroll
            for (int nt = 0; nt < 4; nt++) {
                int cl = wn + nt * 8 + c2;
                float2 v; v.x = acc[mt][nt][half * 2 + 0]; v.y = acc[mt][nt][half * 2 + 1];
                *(float2*)&Cs[r][cl] = v;
            }
        }
    if (tid < 128) { red0[tid] = 0.f; red1[tid] = 0.f; }
    __syncthreads();

    float4 bev = *(const float4*)(be + lane * 4);
    float psum[4] = {0.f, 0.f, 0.f, 0.f}, psq[4] = {0.f, 0.f, 0.f, 0.f};

#pragma unroll
    for (int i = 0; i < 8; i++) {
        int r = warp * 8 + i;
        size_t e = bm + r;
        int s = src[e], d = dst[e];
        float4 pv = unpack_half4(*(const uint2*)(g_PQh + (size_t)s * 256 + lane * 4));
        float4 qv = unpack_half4(*(const uint2*)(g_PQh + (size_t)d * 256 + 128 + lane * 4));
        float4 v = *(const float4*)&Cs[r][lane * 4];
        v.x += pv.x + qv.x + bev.x;
        v.y += pv.y + qv.y + bev.y;
        v.z += pv.z + qv.z + bev.z;
        v.w += pv.w + qv.w + bev.w;
        *(uint2*)(g_MSGh + e * HDIM + lane * 4) = pack_half4(v);
        psum[0] += v.x; psum[1] += v.y; psum[2] += v.z; psum[3] += v.w;
        psq[0] += v.x * v.x; psq[1] += v.y * v.y;
        psq[2] += v.z * v.z; psq[3] += v.w * v.w;
    }

    __syncthreads();
#pragma unroll
    for (int j = 0; j < 4; j++) {
        atomicAdd(&red0[lane * 4 + j], psum[j]);
        atomicAdd(&red1[lane * 4 + j], psq[j]);
    }
    __syncthreads();
    if (tid < 128) {
        atomicAdd(&g_sum[tid], red0[tid]);
        atomicAdd(&g_sq [tid], red1[tid]);
    }
}

// ---------------- BN+ReLU+scatter with vector red ------------------------------
__global__ void scatter_kernel(const int* __restrict__ dst) {
    unsigned t = blockIdx.x * blockDim.x + threadIdx.x;
    size_t e = (size_t)(t >> 5);
    int c4 = (t & 31) * 4;
    if (e < (size_t)N_EDGES) {
        int d = dst[e];
        float4 m = unpack_half4(*(const uint2*)(g_MSGh + e * HDIM + c4));
        float v0 = fmaxf(fmaf(m.x, g_scaleArr[c4 + 0], g_shiftArr[c4 + 0]), 0.f);
        float v1 = fmaxf(fmaf(m.y, g_scaleArr[c4 + 1], g_shiftArr[c4 + 1]), 0.f);
        float v2 = fmaxf(fmaf(m.z, g_scaleArr[c4 + 2], g_shiftArr[c4 + 2]), 0.f);
        float v3 = fmaxf(fmaf(m.w, g_scaleArr[c4 + 3], g_shiftArr[c4 + 3]), 0.f);
        float* p = g_Y + (size_t)d * HDIM + c4;
        asm volatile("red.global.add.v4.f32 [%0], {%1,%2,%3,%4};"
                     :: "l"(p), "f"(v0), "f"(v1), "f"(v2), "f"(v3) : "memory");
    }
}

// ---------------- launch ------------------------------------------------------
extern "C" void kernel_launch(void* const* d_in, const int* in_sizes, int n_in,
                              void* d_out, int out_size) {
    const float* node_rep  = (const float*)d_in[0];
    const float* edge_rep  = (const float*)d_in[1];
    const float* edge_attr = (const float*)d_in[2];
    const int*   eidx      = (const int*)d_in[3];
    const float* W1  = (const float*)d_in[4];
    const float* W2  = (const float*)d_in[5];
    const float* W3  = (const float*)d_in[6];
    const float* We  = (const float*)d_in[7];
    const float* be  = (const float*)d_in[8];
    const float* bng = (const float*)d_in[9];
    const float* bnb = (const float*)d_in[10];
    const float* Wm1 = (const float*)d_in[11];
    const float* g1  = (const float*)d_in[12];
    const float* b1  = (const float*)d_in[13];
    const float* Wm2 = (const float*)d_in[14];
    const float* g2  = (const float*)d_in[15];
    const float* b2  = (const float*)d_in[16];
    const float* Wm3 = (const float*)d_in[17];
    const float* bm3 = (const float*)d_in[18];
    float* out = (float*)d_out;

    const int* src = eidx;
    const int* dst = eidx + N_EDGES;

    float *Y, *H1, *H2, *SUM, *SQ, *SCALE, *SHIFT;
    __half *PQh, *WH;
    cudaGetSymbolAddress((void**)&PQh, g_PQh);
    cudaGetSymbolAddress((void**)&Y,  g_Y);
    cudaGetSymbolAddress((void**)&H1, g_H1);
    cudaGetSymbolAddress((void**)&H2, g_H2);
    cudaGetSymbolAddress((void**)&SUM,   g_sum);
    cudaGetSymbolAddress((void**)&SQ,    g_sq);
    cudaGetSymbolAddress((void**)&SCALE, g_scaleArr);
    cudaGetSymbolAddress((void**)&SHIFT, g_shiftArr);
    cudaGetSymbolAddress((void**)&WH, g_WallH);

    const int GEMM_SMEM = G_PIPE + 2048 + 1024;   // 95232
    const int EDGE_SMEM = E_PIPE + 1024;          // 41984
    cudaFuncSetAttribute(gemm_mma_kernel, cudaFuncAttributeMaxDynamicSharedMemorySize, GEMM_SMEM);
    cudaFuncSetAttribute(edge_msg_kernel, cudaFuncAttributeMaxDynamicSharedMemorySize, EDGE_SMEM);

    const int MBLK = (N_NODES + 127) / 128;  // 782

    prep_kernel<<<(PREP_TOTAL + 255) / 256, 256>>>(W1, W2, W3, We, Wm1, Wm2, Wm3);
    zero_y_stats_kernel<<<4096, 256>>>();

    // fused node linears: PQ = node_rep @ [W1|W2] -> fp16
    gemm_mma_kernel<<<dim3(2, MBLK), 256, GEMM_SMEM>>>(
        node_rep, WH + OFF_NODE, HDIM, PQh, N_NODES, HDIM, 256, 1,
        nullptr, nullptr, nullptr, nullptr, nullptr);

    // edge GEMM (fp16 HMMA) + encoder + gathers + BN stats
    edge_msg_kernel<<<N_EDGES / 64, 256, EDGE_SMEM>>>(edge_rep, edge_attr, src, dst, be);

    bn_finalize_kernel<<<1, 128>>>(bng, bnb, 0, 128, 1.f / (float)N_EDGES);

    // BN + ReLU + scatter-sum
    scatter_kernel<<<(N_EDGES * 32) / 256, 256>>>(dst);

    // MLP layer 1: H1(fp32) = Y @ Wm1
    gemm_mma_kernel<<<dim3(2, MBLK), 256, GEMM_SMEM>>>(
        Y, WH + OFF_M1, HDIM, H1, N_NODES, HDIM, H2DIM, 0,
        nullptr, nullptr, nullptr, SUM + 128, SQ + 128);
    bn_finalize_kernel<<<2, 128>>>(g1, b1, 128, 256, 1.f / (float)N_NODES);

    // MLP layer 2: H2(fp32) = relu(bn1(H1)) @ Wm2
    gemm_mma_kernel<<<dim3(2, MBLK), 256, GEMM_SMEM>>>(
        H1, WH + OFF_M2, H2DIM, H2, N_NODES, H2DIM, H2DIM, 0,
        SCALE + 128, SHIFT + 128, nullptr, SUM + 384, SQ + 384);
    bn_finalize_kernel<<<2, 128>>>(g2, b2, 384, 256, 1.f / (float)N_NODES);

    // MLP layer 3: out = relu(bn2(H2)) @ Wm3 + bm3
    gemm_mma_kernel<<<dim3(1, MBLK), 256, GEMM_SMEM>>>(
        H2, WH + OFF_M3, H2DIM, out, N_NODES, H2DIM, HDIM, 0,
        SCALE + 384, SHIFT + 384, bm3, nullptr, nullptr);
}

// round 14
// speedup vs baseline: 1.2465x; 1.0607x over previous
#include <cuda_runtime.h>
#include <cuda_fp16.h>
#include <cstdint>

#define N_NODES 100000
#define N_EDGES 640000
#define HDIM 128
#define H2DIM 256
#define EDIM 16

// ---------------- scratch (device globals) ------------------------------------
__device__ __half g_PQh [(size_t)N_NODES * 256];   // fp16: [0:128]=node@W1, [128:256]=node@W2
__device__ __half g_MSGh[(size_t)N_EDGES * HDIM];  // fp16 pre-BN messages
__device__ float  g_Y   [(size_t)N_NODES * HDIM];  // scatter target (fp32 accum)
__device__ float  g_H1  [(size_t)N_NODES * H2DIM]; // fp32 MLP intermediates
__device__ float  g_H2  [(size_t)N_NODES * H2DIM];
// BN stat slots: [0,128)=msg, [128,384)=bn1, [384,640)=bn2
__device__ float g_sum[640];
__device__ float g_sq [640];
__device__ float g_scaleArr[128];   // msg BN only (scatter)
__device__ float g_shiftArr[128];

// fp16 weights in [n][k] layout for HMMA (B operand = col-major)
#define OFF_NODE 0        // [256 n][128 k]  W1 | W2
#define OFF_M1   32768    // [256 n][128 k]
#define OFF_M2   65536    // [256 n][256 k]
#define OFF_M3   131072   // [128 n][256 k]
#define WH_TOTAL 163840
__device__ __half g_WallH[WH_TOTAL];
// edge weights fp16 [n][k]: k 0..127 = W3, 128..143 = We, stride 160
#define WEH_STRIDE 160
__device__ __half g_WedgeH[128 * WEH_STRIDE];

// ---------------- helpers ------------------------------------------------------
__device__ __forceinline__ void mma_f16(float* c, const unsigned* a, const unsigned* b) {
    asm volatile(
        "mma.sync.aligned.m16n8k16.row.col.f32.f16.f16.f32 "
        "{%0,%1,%2,%3}, {%4,%5,%6,%7}, {%8,%9}, {%0,%1,%2,%3};"
        : "+f"(c[0]), "+f"(c[1]), "+f"(c[2]), "+f"(c[3])
        : "r"(a[0]), "r"(a[1]), "r"(a[2]), "r"(a[3]), "r"(b[0]), "r"(b[1]));
}

__device__ __forceinline__ void cp16(uint32_t dst, const void* src, bool pred) {
    int sz = pred ? 16 : 0;
    asm volatile("cp.async.cg.shared.global [%0], [%1], 16, %2;"
                 :: "r"(dst), "l"(src), "r"(sz));
}
__device__ __forceinline__ void cp_commit() { asm volatile("cp.async.commit_group;"); }
template <int N> __device__ __forceinline__ void cp_wait() {
    asm volatile("cp.async.wait_group %0;" :: "n"(N));
}
__device__ __forceinline__ uint32_t s2u(const void* p) {
    uint32_t a;
    asm("{ .reg .u64 t; cvta.to.shared.u64 t, %1; cvt.u32.u64 %0, t; }" : "=r"(a) : "l"(p));
    return a;
}
__device__ __forceinline__ uint2 pack_half4(float4 v) {
    __half2 h0 = __floats2half2_rn(v.x, v.y);
    __half2 h1 = __floats2half2_rn(v.z, v.w);
    uint2 u;
    u.x = *(unsigned*)&h0;
    u.y = *(unsigned*)&h1;
    return u;
}
__device__ __forceinline__ float4 unpack_half4(uint2 u) {
    __half2 h0 = *(__half2*)&u.x;
    __half2 h1 = *(__half2*)&u.y;
    float2 f0 = __half22float2(h0);
    float2 f1 = __half22float2(h1);
    return make_float4(f0.x, f0.y, f1.x, f1.y);
}
__device__ __forceinline__ unsigned h2_from_f2(float2 f) {
    __half2 h = __float22half2_rn(f);
    return *(unsigned*)&h;
}

// dense GEMM smem: A 128x40 fp32, B 128x40 fp16, 3 stages (conflict-free)
#define G_ASTR 40
#define G_AS_STAGE (128 * G_ASTR * 4)   // 20480
#define G_BSH_STAGE (128 * 40 * 2)      // 10240
#define G_AS_BYTES (3 * G_AS_STAGE)     // 61440
#define G_BS_BYTES (3 * G_BSH_STAGE)    // 30720
#define G_PIPE (G_AS_BYTES + G_BS_BYTES)  // 92160
// edge smem: A 64x40 fp32, B 128x40 fp16, 2 stages
#define E_ASTR 40
#define E_AS_STAGE (64 * E_ASTR * 4)   // 10240
#define E_BSH_STAGE 10240              // 128*40*2
#define E_AS_BYTES (2 * E_AS_STAGE)    // 20480
#define E_PIPE (E_AS_BYTES + 2 * E_BSH_STAGE)  // 40960

// ---------------- prep: weight convert + zero Y/stats ---------------------------
#define PREP_TOTAL (WH_TOTAL + 128 * WEH_STRIDE)   // 184320
__global__ void prep_kernel(const float* __restrict__ W1, const float* __restrict__ W2,
                            const float* __restrict__ W3, const float* __restrict__ We,
                            const float* __restrict__ Wm1, const float* __restrict__ Wm2,
                            const float* __restrict__ Wm3) {
    size_t i = (size_t)blockIdx.x * blockDim.x + threadIdx.x;
    if (i < 32768) {
        int n = (int)i >> 7, k = (int)i & 127;
        float v = (n < 128) ? W1[k * 128 + n] : W2[k * 128 + (n - 128)];
        g_WallH[OFF_NODE + i] = __float2half_rn(v);
    } else if (i < 65536) {
        int j = (int)i - 32768;
        int n = j >> 7, k = j & 127;
        g_WallH[OFF_M1 + j] = __float2half_rn(Wm1[k * 256 + n]);
    } else if (i < 131072) {
        int j = (int)i - 65536;
        int n = j >> 8, k = j & 255;
        g_WallH[OFF_M2 + j] = __float2half_rn(Wm2[k * 256 + n]);
    } else if (i < WH_TOTAL) {
        int j = (int)i - 131072;
        int n = j >> 8, k = j & 255;
        g_WallH[OFF_M3 + j] = __float2half_rn(Wm3[k * 128 + n]);
    } else if (i < PREP_TOTAL) {
        int j = (int)i - WH_TOTAL;
        int n = j / WEH_STRIDE, k = j % WEH_STRIDE;
        float v = 0.f;
        if (k < 128)      v = W3[k * 128 + n];
        else if (k < 144) v = We[(k - 128) * 128 + n];
        g_WedgeH[j] = __float2half_rn(v);
    }
    const size_t tot = (size_t)N_NODES * HDIM;
    const size_t stride = (size_t)gridDim.x * blockDim.x;
    for (size_t p = i; p < tot; p += stride) g_Y[p] = 0.f;
    if (i < 640) { g_sum[i] = 0.f; g_sq[i] = 0.f; }
}

__global__ void bn_finalize_kernel(const float* __restrict__ g,
                                   const float* __restrict__ b, float invCnt) {
    int c = threadIdx.x;
    float mean = g_sum[c] * invCnt;
    float var  = fmaxf(g_sq[c] * invCnt - mean * mean, 0.f);
    float a = g[c] * rsqrtf(var + 1e-5f);
    g_scaleArr[c] = a;
    g_shiftArr[c] = fmaf(-mean, a, b[c]);
}

extern __shared__ char smem_raw[];

// ---------------- 3-stage pipelined fp16-HMMA GEMM with fused BN ----------------
// C[M,NC] = act(A) @ Wh^T (+cBias); Wh fp16 [n][k].
// BN-in is computed IN-KERNEL from raw stats (bnG,bnB,rawSum,rawSq,invCnt):
// act(x) = relu(scale[k]*x + shift[k]). outHalf: fp16 C. sSum/sSq: stats out.
__global__ void __launch_bounds__(256, 2) gemm_mma_kernel(
    const float* __restrict__ A, const __half* __restrict__ Wh, int KSTR,
    void* __restrict__ Cout, int M, int K, int NC, int outHalf,
    const float* __restrict__ bnG, const float* __restrict__ bnB,
    const float* __restrict__ rawSum, const float* __restrict__ rawSq, float invCnt,
    const float* __restrict__ cBias,
    float* __restrict__ sSum, float* __restrict__ sSq)
{
    float  (*As)[128][G_ASTR] = reinterpret_cast<float(*)[128][G_ASTR]>(smem_raw);
    __half (*Bs)[128][40]     = reinterpret_cast<__half(*)[128][40]>(smem_raw + G_AS_BYTES);
    float  (*Cs)[132]         = reinterpret_cast<float(*)[132]>(smem_raw);   // overlay
    float* scs  = (float*)(smem_raw + G_PIPE);          // 256
    float* shs  = scs + 256;                            // 256
    float* red0 = shs + 256;                            // 128
    float* red1 = red0 + 128;                           // 128

    const int tid = threadIdx.x, lane = tid & 31, warp = tid >> 5;
    const int wm = (warp & 3) * 32, wn = (warp >> 2) * 64;
    const int g  = lane >> 2;
    const int c2 = (lane & 3) * 2;
    const int bm = blockIdx.y * 128, bn = blockIdx.x * 128;
    const bool useBN = (bnG != nullptr);

    const uint32_t AsAddr = s2u(smem_raw);
    const uint32_t BsAddr = AsAddr + G_AS_BYTES;

    // fused BN finalize: compute scale/shift from raw column stats
    if (useBN && tid < K) {
        float mean = rawSum[tid] * invCnt;
        float var  = fmaxf(rawSq[tid] * invCnt - mean * mean, 0.f);
        float a = bnG[tid] * rsqrtf(var + 1e-5f);
        scs[tid] = a;
        shs[tid] = fmaf(-mean, a, bnB[tid]);
    }

    auto issue_copy = [&](int t) {
        const int s = t % 3;
        const int k0 = t * 32;
#pragma unroll
        for (int l = 0; l < 4; l++) {
            int c = tid + l * 256;
            int row = c >> 3, cc = c & 7;
            int grow = bm + row;
            const float* src = A + (size_t)grow * K + k0 + cc * 4;
            uint32_t dst = AsAddr + (uint32_t)(s * G_AS_STAGE + (row * G_ASTR + cc * 4) * 4);
            cp16(dst, src, grow < M);
        }
#pragma unroll
        for (int l = 0; l < 2; l++) {
            int c = tid + l * 256;
            int row = c >> 2, cc = c & 3;
            const __half* src = Wh + (size_t)(bn + row) * KSTR + k0 + cc * 8;
            uint32_t dst = BsAddr + (uint32_t)(s * G_BSH_STAGE + (row * 40 + cc * 8) * 2);
            cp16(dst, src, true);
        }
        cp_commit();
    };

    float acc[2][8][4];
#pragma unroll
    for (int mt = 0; mt < 2; mt++)
#pragma unroll
        for (int nt = 0; nt < 8; nt++)
#pragma unroll
            for (int i = 0; i < 4; i++) acc[mt][nt][i] = 0.f;

    const int T = K >> 5;
    issue_copy(0);
    if (T > 1) issue_copy(1);

    for (int t = 0; t < T; t++) {
        if (t + 2 < T)      { issue_copy(t + 2); cp_wait<2>(); }
        else if (t + 1 < T) { cp_wait<1>(); }
        else                { cp_wait<0>(); }
        __syncthreads();
        const int s = t % 3;
        const int k0 = t * 32;
#pragma unroll
        for (int ks = 0; ks < 2; ks++) {
            const int kk = ks * 16;
            float2 scLo = make_float2(1.f, 1.f), shLo = make_float2(0.f, 0.f);
            float2 scHi = make_float2(1.f, 1.f), shHi = make_float2(0.f, 0.f);
            if (useBN) {
                scLo = *(const float2*)&scs[k0 + kk + c2];
                shLo = *(const float2*)&shs[k0 + kk + c2];
                scHi = *(const float2*)&scs[k0 + kk + c2 + 8];
                shHi = *(const float2*)&shs[k0 + kk + c2 + 8];
            }
            unsigned af[2][4], bf[8][2];
#pragma unroll
            for (int mt = 0; mt < 2; mt++) {
                int m = wm + mt * 16 + g;
                float2 a0 = *(const float2*)&As[s][m    ][kk + c2];
                float2 a1 = *(const float2*)&As[s][m + 8][kk + c2];
                float2 a2 = *(const float2*)&As[s][m    ][kk + c2 + 8];
                float2 a3 = *(const float2*)&As[s][m + 8][kk + c2 + 8];
                if (useBN) {
                    a0.x = fmaxf(fmaf(a0.x, scLo.x, shLo.x), 0.f);
                    a0.y = fmaxf(fmaf(a0.y, scLo.y, shLo.y), 0.f);
                    a1.x = fmaxf(fmaf(a1.x, scLo.x, shLo.x), 0.f);
                    a1.y = fmaxf(fmaf(a1.y, scLo.y, shLo.y), 0.f);
                    a2.x = fmaxf(fmaf(a2.x, scHi.x, shHi.x), 0.f);
                    a2.y = fmaxf(fmaf(a2.y, scHi.y, shHi.y), 0.f);
                    a3.x = fmaxf(fmaf(a3.x, scHi.x, shHi.x), 0.f);
                    a3.y = fmaxf(fmaf(a3.y, scHi.y, shHi.y), 0.f);
                }
                af[mt][0] = h2_from_f2(a0);
                af[mt][1] = h2_from_f2(a1);
                af[mt][2] = h2_from_f2(a2);
                af[mt][3] = h2_from_f2(a3);
            }
#pragma unroll
            for (int nt = 0; nt < 8; nt++) {
                int n = wn + nt * 8 + g;
                bf[nt][0] = *(const unsigned*)&Bs[s][n][kk + c2];
                bf[nt][1] = *(const unsigned*)&Bs[s][n][kk + c2 + 8];
            }
#pragma unroll
            for (int mt = 0; mt < 2; mt++)
#pragma unroll
                for (int nt = 0; nt < 8; nt++)
                    mma_f16(acc[mt][nt], af[mt], bf[nt]);
        }
        __syncthreads();
    }

    // ---------------- epilogue: stage -> smem, warp-per-row coalesced ----------
#pragma unroll
    for (int mt = 0; mt < 2; mt++)
#pragma unroll
        for (int half = 0; half < 2; half++) {
            int r = wm + mt * 16 + g + half * 8;
#pragma unroll
            for (int nt = 0; nt < 8; nt++) {
                int cl = wn + nt * 8 + c2;
                float2 v; v.x = acc[mt][nt][half * 2 + 0]; v.y = acc[mt][nt][half * 2 + 1];
                *(float2*)&Cs[r][cl] = v;
            }
        }
    if (sSum && tid < 128) { red0[tid] = 0.f; red1[tid] = 0.f; }
    __syncthreads();

    float4 bias = make_float4(0.f, 0.f, 0.f, 0.f);
    if (cBias) bias = *(const float4*)(cBias + bn + lane * 4);
    float psum[4] = {0.f, 0.f, 0.f, 0.f}, psq[4] = {0.f, 0.f, 0.f, 0.f};

#pragma unroll
    for (int i = 0; i < 16; i++) {
        int r = warp * 16 + i;
        int R = bm + r;
        if (R < M) {
            float4 v = *(const float4*)&Cs[r][lane * 4];
            v.x += bias.x; v.y += bias.y; v.z += bias.z; v.w += bias.w;
            if (outHalf) {
                __half* Ch = (__half*)Cout;
                *(uint2*)(Ch + (size_t)R * NC + bn + lane * 4) = pack_half4(v);
            } else {
                float* Cf = (float*)Cout;
                *(float4*)(Cf + (size_t)R * NC + bn + lane * 4) = v;
            }
            psum[0] += v.x; psum[1] += v.y; psum[2] += v.z; psum[3] += v.w;
            psq[0] += v.x * v.x; psq[1] += v.y * v.y;
            psq[2] += v.z * v.z; psq[3] += v.w * v.w;
        }
    }

    if (sSum) {
        __syncthreads();
#pragma unroll
        for (int j = 0; j < 4; j++) {
            atomicAdd(&red0[lane * 4 + j], psum[j]);
            atomicAdd(&red1[lane * 4 + j], psq[j]);
        }
        __syncthreads();
        if (tid < 128) {
            atomicAdd(&sSum[bn + tid], red0[tid]);
            atomicAdd(&sSq [bn + tid], red1[tid]);
        }
    }
}

// ---------------- edge message kernel: fp16 HMMA, occ-4 experiment --------------
__global__ void __launch_bounds__(256, 4) edge_msg_kernel(
    const float* __restrict__ edge_rep, const float* __restrict__ edge_attr,
    const int* __restrict__ src, const int* __restrict__ dst,
    const float* __restrict__ be)
{
    float  (*As)[64][E_ASTR] = reinterpret_cast<float(*)[64][E_ASTR]>(smem_raw);
    __half (*Bs)[128][40]    = reinterpret_cast<__half(*)[128][40]>(smem_raw + E_AS_BYTES);
    float  (*Cs)[132]        = reinterpret_cast<float(*)[132]>(smem_raw);   // overlay
    float* red0 = (float*)(smem_raw + E_PIPE);
    float* red1 = red0 + 128;

    const int tid = threadIdx.x, lane = tid & 31, warp = tid >> 5;
    const int wm = (warp & 1) * 32, wn = (warp >> 1) * 32;
    const int g  = lane >> 2;
    const int c2 = (lane & 3) * 2;
    const size_t bm = (size_t)blockIdx.x * 64;

    const uint32_t AsAddr = s2u(smem_raw);
    const uint32_t BsAddr = AsAddr + E_AS_BYTES;

    if (tid < 128) {
        int e0 = (int)bm + (tid >> 1);
        const __half* row = (tid & 1) ? (g_PQh + (size_t)dst[e0] * 256 + 128)
                                      : (g_PQh + (size_t)src[e0] * 256);
        asm volatile("prefetch.global.L2 [%0];" :: "l"(row));
        asm volatile("prefetch.global.L2 [%0];" :: "l"(row + 64));
    }

    auto issue_copy = [&](int t) {
        const int s = t & 1;
        if (t < 4) {
            const int k0 = t * 32;
#pragma unroll
            for (int l = 0; l < 2; l++) {
                int c = tid + l * 256;
                int row = c >> 3, cc = c & 7;
                const float* sp = edge_rep + (bm + row) * HDIM + k0 + cc * 4;
                uint32_t dp = AsAddr + (uint32_t)(s * E_AS_STAGE + (row * E_ASTR + cc * 4) * 4);
                cp16(dp, sp, true);
            }
#pragma unroll
            for (int l = 0; l < 2; l++) {
                int c = tid + l * 256;
                int row = c >> 2, cc = c & 3;
                const __half* sp = g_WedgeH + (size_t)row * WEH_STRIDE + k0 + cc * 8;
                uint32_t dp = BsAddr + (uint32_t)(s * E_BSH_STAGE + (row * 40 + cc * 8) * 2);
                cp16(dp, sp, true);
            }
        } else {
            {
                int row = tid >> 2, cc = tid & 3;
                const float* sp = edge_attr + (bm + row) * EDIM + cc * 4;
                uint32_t dp = AsAddr + (uint32_t)(s * E_AS_STAGE + (row * E_ASTR + cc * 4) * 4);
                cp16(dp, sp, true);
            }
            {
                int row = tid >> 1, cc = tid & 1;
                const __half* sp = g_WedgeH + (size_t)row * WEH_STRIDE + 128 + cc * 8;
                uint32_t dp = BsAddr + (uint32_t)(s * E_BSH_STAGE + (row * 40 + cc * 8) * 2);
                cp16(dp, sp, true);
            }
        }
        cp_commit();
    };

    float acc[2][4][4];
#pragma unroll
    for (int mt = 0; mt < 2; mt++)
#pragma unroll
        for (int nt = 0; nt < 4; nt++)
#pragma unroll
            for (int i = 0; i < 4; i++) acc[mt][nt][i] = 0.f;

    issue_copy(0);

#pragma unroll
    for (int t = 0; t < 5; t++) {
        cp_wait<0>();
        __syncthreads();
        if (t + 1 < 5) issue_copy(t + 1);
        const int s = t & 1;
        const int ksteps = (t < 4) ? 2 : 1;
#pragma unroll
        for (int ks = 0; ks < 2; ks++) {
            if (ks >= ksteps) break;
            const int kk = ks * 16;
            unsigned af[2][4], bf[4][2];
#pragma unroll
            for (int mt = 0; mt < 2; mt++) {
                int m = wm + mt * 16 + g;
                af[mt][0] = h2_from_f2(*(const float2*)&As[s][m    ][kk + c2]);
                af[mt][1] = h2_from_f2(*(const float2*)&As[s][m + 8][kk + c2]);
                af[mt][2] = h2_from_f2(*(const float2*)&As[s][m    ][kk + c2 + 8]);
                af[mt][3] = h2_from_f2(*(const float2*)&As[s][m + 8][kk + c2 + 8]);
            }
#pragma unroll
            for (int nt = 0; nt < 4; nt++) {
                int n = wn + nt * 8 + g;
                bf[nt][0] = *(const unsigned*)&Bs[s][n][kk + c2];
                bf[nt][1] = *(const unsigned*)&Bs[s][n][kk + c2 + 8];
            }
#pragma unroll
            for (int mt = 0; mt < 2; mt++)
#pragma unroll
                for (int nt = 0; nt < 4; nt++)
                    mma_f16(acc[mt][nt], af[mt], bf[nt]);
        }
        __syncthreads();
    }

#pragma unroll
    for (int mt = 0; mt < 2; mt++)
#pragma unroll
        for (int half = 0; half < 2; half++) {
            int r = wm + mt * 16 + g + half * 8;
#pragma unroll
            for (int nt = 0; nt < 4; nt++) {
                int cl = wn + nt * 8 + c2;
                float2 v; v.x = acc[mt][nt][half * 2 + 0]; v.y = acc[mt][nt][half * 2 + 1];
                *(float2*)&Cs[r][cl] = v;
            }
        }
    if (tid < 128) { red0[tid] = 0.f; red1[tid] = 0.f; }
    __syncthreads();

    float4 bev = *(const float4*)(be + lane * 4);
    float psum[4] = {0.f, 0.f, 0.f, 0.f}, psq[4] = {0.f, 0.f, 0.f, 0.f};

#pragma unroll
    for (int i = 0; i < 8; i++) {
        int r = warp * 8 + i;
        size_t e = bm + r;
        int s = src[e], d = dst[e];
        float4 pv = unpack_half4(*(const uint2*)(g_PQh + (size_t)s * 256 + lane * 4));
        float4 qv = unpack_half4(*(const uint2*)(g_PQh + (size_t)d * 256 + 128 + lane * 4));
        float4 v = *(const float4*)&Cs[r][lane * 4];
        v.x += pv.x + qv.x + bev.x;
        v.y += pv.y + qv.y + bev.y;
        v.z += pv.z + qv.z + bev.z;
        v.w += pv.w + qv.w + bev.w;
        *(uint2*)(g_MSGh + e * HDIM + lane * 4) = pack_half4(v);
        psum[0] += v.x; psum[1] += v.y; psum[2] += v.z; psum[3] += v.w;
        psq[0] += v.x * v.x; psq[1] += v.y * v.y;
        psq[2] += v.z * v.z; psq[3] += v.w * v.w;
    }

    __syncthreads();
#pragma unroll
    for (int j = 0; j < 4; j++) {
        atomicAdd(&red0[lane * 4 + j], psum[j]);
        atomicAdd(&red1[lane * 4 + j], psq[j]);
    }
    __syncthreads();
    if (tid < 128) {
        atomicAdd(&g_sum[tid], red0[tid]);
        atomicAdd(&g_sq [tid], red1[tid]);
    }
}

// ---------------- BN+ReLU+scatter with vector red ------------------------------
__global__ void scatter_kernel(const int* __restrict__ dst) {
    unsigned t = blockIdx.x * blockDim.x + threadIdx.x;
    size_t e = (size_t)(t >> 5);
    int c4 = (t & 31) * 4;
    if (e < (size_t)N_EDGES) {
        int d = dst[e];
        float4 m = unpack_half4(*(const uint2*)(g_MSGh + e * HDIM + c4));
        float v0 = fmaxf(fmaf(m.x, g_scaleArr[c4 + 0], g_shiftArr[c4 + 0]), 0.f);
        float v1 = fmaxf(fmaf(m.y, g_scaleArr[c4 + 1], g_shiftArr[c4 + 1]), 0.f);
        float v2 = fmaxf(fmaf(m.z, g_scaleArr[c4 + 2], g_shiftArr[c4 + 2]), 0.f);
        float v3 = fmaxf(fmaf(m.w, g_scaleArr[c4 + 3], g_shiftArr[c4 + 3]), 0.f);
        float* p = g_Y + (size_t)d * HDIM + c4;
        asm volatile("red.global.add.v4.f32 [%0], {%1,%2,%3,%4};"
                     :: "l"(p), "f"(v0), "f"(v1), "f"(v2), "f"(v3) : "memory");
    }
}

// ---------------- launch ------------------------------------------------------
extern "C" void kernel_launch(void* const* d_in, const int* in_sizes, int n_in,
                              void* d_out, int out_size) {
    const float* node_rep  = (const float*)d_in[0];
    const float* edge_rep  = (const float*)d_in[1];
    const float* edge_attr = (const float*)d_in[2];
    const int*   eidx      = (const int*)d_in[3];
    const float* W1  = (const float*)d_in[4];
    const float* W2  = (const float*)d_in[5];
    const float* W3  = (const float*)d_in[6];
    const float* We  = (const float*)d_in[7];
    const float* be  = (const float*)d_in[8];
    const float* bng = (const float*)d_in[9];
    const float* bnb = (const float*)d_in[10];
    const float* Wm1 = (const float*)d_in[11];
    const float* g1  = (const float*)d_in[12];
    const float* b1  = (const float*)d_in[13];
    const float* Wm2 = (const float*)d_in[14];
    const float* g2  = (const float*)d_in[15];
    const float* b2  = (const float*)d_in[16];
    const float* Wm3 = (const float*)d_in[17];
    const float* bm3 = (const float*)d_in[18];
    float* out = (float*)d_out;

    const int* src = eidx;
    const int* dst = eidx + N_EDGES;

    float *Y, *H1, *H2, *SUM, *SQ;
    __half *PQh, *WH;
    cudaGetSymbolAddress((void**)&PQh, g_PQh);
    cudaGetSymbolAddress((void**)&Y,  g_Y);
    cudaGetSymbolAddress((void**)&H1, g_H1);
    cudaGetSymbolAddress((void**)&H2, g_H2);
    cudaGetSymbolAddress((void**)&SUM, g_sum);
    cudaGetSymbolAddress((void**)&SQ,  g_sq);
    cudaGetSymbolAddress((void**)&WH,  g_WallH);

    const int GEMM_SMEM = G_PIPE + 2048 + 1024;   // 95232
    const int EDGE_SMEM = E_PIPE + 1024;          // 41984
    cudaFuncSetAttribute(gemm_mma_kernel, cudaFuncAttributeMaxDynamicSharedMemorySize, GEMM_SMEM);
    cudaFuncSetAttribute(edge_msg_kernel, cudaFuncAttributeMaxDynamicSharedMemorySize, EDGE_SMEM);

    const int MBLK = (N_NODES + 127) / 128;  // 782
    const float invN = 1.f / (float)N_NODES;

    prep_kernel<<<4096, 256>>>(W1, W2, W3, We, Wm1, Wm2, Wm3);

    // fused node linears: PQ = node_rep @ [W1|W2] -> fp16
    gemm_mma_kernel<<<dim3(2, MBLK), 256, GEMM_SMEM>>>(
        node_rep, WH + OFF_NODE, HDIM, PQh, N_NODES, HDIM, 256, 1,
        nullptr, nullptr, nullptr, nullptr, 0.f, nullptr, nullptr, nullptr);

    // edge GEMM (fp16 HMMA, occ-4) + encoder + gathers + BN stats
    edge_msg_kernel<<<N_EDGES / 64, 256, EDGE_SMEM>>>(edge_rep, edge_attr, src, dst, be);

    bn_finalize_kernel<<<1, 128>>>(bng, bnb, 1.f / (float)N_EDGES);

    // BN + ReLU + scatter-sum
    scatter_kernel<<<(N_EDGES * 32) / 256, 256>>>(dst);

    // MLP layer 1: H1 = Y @ Wm1, stats -> slot 128
    gemm_mma_kernel<<<dim3(2, MBLK), 256, GEMM_SMEM>>>(
        Y, WH + OFF_M1, HDIM, H1, N_NODES, HDIM, H2DIM, 0,
        nullptr, nullptr, nullptr, nullptr, 0.f, nullptr, SUM + 128, SQ + 128);

    // MLP layer 2: H2 = relu(bn1(H1)) @ Wm2 (bn1 finalize fused in-kernel)
    gemm_mma_kernel<<<dim3(2, MBLK), 256, GEMM_SMEM>>>(
        H1, WH + OFF_M2, H2DIM, H2, N_NODES, H2DIM, H2DIM, 0,
        g1, b1, SUM + 128, SQ + 128, invN, nullptr, SUM + 384, SQ + 384);

    // MLP layer 3: out = relu(bn2(H2)) @ Wm3 + bm3 (bn2 finalize fused in-kernel)
    gemm_mma_kernel<<<dim3(1, MBLK), 256, GEMM_SMEM>>>(
        H2, WH + OFF_M3, H2DIM, out, N_NODES, H2DIM, HDIM, 0,
        g2, b2, SUM + 384, SQ + 384, invN, bm3, nullptr, nullptr);
}